// round 13
// baseline (speedup 1.0000x reference)
#include <cuda_runtime.h>
#include <cuda_bf16.h>
#include <math.h>

#define MAXN 100000
#define MAXE 1600000
#define SCAN_CHUNK 1024

// ---------------- scratch ---------------------------------------------------
__device__ __align__(16) int   g_edeg[MAXN];
__device__ __align__(16) float g_dis[MAXN];
__device__ __align__(16) int   g_off[MAXN + 1];   // after fill: inclusive ends
__device__ __align__(16) int   g_col[MAXE];
__device__ __align__(16) int   g_bsum[128];
__device__ __align__(16) __nv_bfloat16 g_hA[(size_t)MAXN * 128];
__device__ __align__(16) __nv_bfloat16 g_hB[(size_t)MAXN * 128];
__device__ __align__(16) float g_pooled[64];

__device__ __forceinline__ __nv_bfloat162 u2bf2(unsigned u) {
    return *reinterpret_cast<__nv_bfloat162*>(&u);
}

// ---------------- zero scratch ----------------------------------------------
__global__ void zero_kernel(int n) {
    int i = blockIdx.x * blockDim.x + threadIdx.x;
    int stride = gridDim.x * blockDim.x;
    for (int k = i; k < n; k += stride) g_edeg[k] = 0;
    if (i < 64) g_pooled[i] = 0.0f;
}

// ---------------- degree histogram over dst (int4 vectorized) ---------------
__global__ void degree_kernel(const int* __restrict__ dst, int e) {
    int i = blockIdx.x * blockDim.x + threadIdx.x;
    int stride = gridDim.x * blockDim.x;
    int e4 = e >> 2;
    for (int k = i; k < e4; k += stride) {
        int4 d = reinterpret_cast<const int4*>(dst)[k];
        atomicAdd(&g_edeg[d.x], 1);
        atomicAdd(&g_edeg[d.y], 1);
        atomicAdd(&g_edeg[d.z], 1);
        atomicAdd(&g_edeg[d.w], 1);
    }
    if (i < (e & 3)) atomicAdd(&g_edeg[dst[e4 * 4 + i]], 1);
}

// ---------------- scan phase A: per-block sums + dis ------------------------
__global__ void scanA_kernel(int n) {
    __shared__ int ssum[8];
    int base = blockIdx.x * SCAN_CHUNK + threadIdx.x * 4;
    int s = 0;
#pragma unroll
    for (int j = 0; j < 4; j++) {
        int idx = base + j;
        if (idx < n) {
            int d = g_edeg[idx];
            s += d;
            g_dis[idx] = rsqrtf((float)(d + 1));
        }
    }
#pragma unroll
    for (int o = 16; o > 0; o >>= 1) s += __shfl_down_sync(0xffffffffu, s, o);
    if ((threadIdx.x & 31) == 0) ssum[threadIdx.x >> 5] = s;
    __syncthreads();
    if (threadIdx.x == 0) {
        int t = 0;
#pragma unroll
        for (int w = 0; w < 8; w++) t += ssum[w];
        g_bsum[blockIdx.x] = t;
    }
}

// ---------------- x -> bf16, prescaled by dis[row] (vectorized x8) ----------
__global__ void cvt_kernel(const float* __restrict__ x, __nv_bfloat16* __restrict__ o,
                           int total8) {
    int i = blockIdx.x * blockDim.x + threadIdx.x;
    int stride = gridDim.x * blockDim.x;
    for (int k = i; k < total8; k += stride) {
        int base = k * 8;
        float dd = g_dis[base >> 6];
        float4 a = *reinterpret_cast<const float4*>(x + base);
        float4 b = *reinterpret_cast<const float4*>(x + base + 4);
        __nv_bfloat162 p0 = __floats2bfloat162_rn(a.x * dd, a.y * dd);
        __nv_bfloat162 p1 = __floats2bfloat162_rn(a.z * dd, a.w * dd);
        __nv_bfloat162 p2 = __floats2bfloat162_rn(b.x * dd, b.y * dd);
        __nv_bfloat162 p3 = __floats2bfloat162_rn(b.z * dd, b.w * dd);
        uint4 r;
        r.x = *reinterpret_cast<unsigned*>(&p0);
        r.y = *reinterpret_cast<unsigned*>(&p1);
        r.z = *reinterpret_cast<unsigned*>(&p2);
        r.w = *reinterpret_cast<unsigned*>(&p3);
        *reinterpret_cast<uint4*>(o + base) = r;
    }
}

// ---------------- scan phase C (with inline block-sum scan) -----------------
__global__ void scanC_kernel(int nb, int n) {
    __shared__ int sb[128];
    __shared__ int sh[256];
    int t = threadIdx.x;
    if (t < 128) sb[t] = (t < nb) ? g_bsum[t] : 0;
    __syncthreads();
#pragma unroll
    for (int o = 1; o < 128; o <<= 1) {
        int u = (t >= o && t < 128) ? sb[t - o] : 0;
        __syncthreads();
        if (t < 128) sb[t] += u;
        __syncthreads();
    }
    int boff = (blockIdx.x == 0) ? 0 : sb[blockIdx.x - 1];
    if (blockIdx.x == 0 && t == 0) g_off[n] = sb[127];

    int base = blockIdx.x * SCAN_CHUNK + t * 4;
    int d[4];
    int s = 0;
#pragma unroll
    for (int j = 0; j < 4; j++) {
        int idx = base + j;
        d[j] = (idx < n) ? g_edeg[idx] : 0;
        s += d[j];
    }
    sh[t] = s;
    __syncthreads();
#pragma unroll
    for (int o = 1; o < 256; o <<= 1) {
        int u = (t >= o) ? sh[t - o] : 0;
        __syncthreads();
        sh[t] += u;
        __syncthreads();
    }
    int run = boff + sh[t] - s;
#pragma unroll
    for (int j = 0; j < 4; j++) {
        int idx = base + j;
        if (idx < n) g_off[idx] = run;
        run += d[j];
    }
}

// ---------------- CSR fill (in-place cursor on g_off, int4 vectorized) ------
__global__ void fill_kernel(const int* __restrict__ src,
                            const int* __restrict__ dst, int e) {
    int i = blockIdx.x * blockDim.x + threadIdx.x;
    int stride = gridDim.x * blockDim.x;
    int e4 = e >> 2;
    for (int k = i; k < e4; k += stride) {
        int4 d = reinterpret_cast<const int4*>(dst)[k];
        int4 s = reinterpret_cast<const int4*>(src)[k];
        g_col[atomicAdd(&g_off[d.x], 1)] = s.x;
        g_col[atomicAdd(&g_off[d.y], 1)] = s.y;
        g_col[atomicAdd(&g_off[d.z], 1)] = s.z;
        g_col[atomicAdd(&g_off[d.w], 1)] = s.w;
    }
    if (i < (e & 3)) {
        int k = e4 * 4 + i;
        g_col[atomicAdd(&g_off[dst[k]], 1)] = src[k];
    }
}

// ---------------- tensor-core GEMM ------------------------------------------
__device__ __forceinline__ unsigned smem_u32(const void* p) {
    return (unsigned)__cvta_generic_to_shared(p);
}
__device__ __forceinline__ void ldsm_x4(unsigned& r0, unsigned& r1, unsigned& r2,
                                        unsigned& r3, unsigned addr) {
    asm volatile("ldmatrix.sync.aligned.m8n8.x4.shared.b16 {%0,%1,%2,%3}, [%4];\n"
                 : "=r"(r0), "=r"(r1), "=r"(r2), "=r"(r3) : "r"(addr));
}
__device__ __forceinline__ void ldsm_x4_t(unsigned& r0, unsigned& r1, unsigned& r2,
                                          unsigned& r3, unsigned addr) {
    asm volatile("ldmatrix.sync.aligned.m8n8.x4.trans.shared.b16 {%0,%1,%2,%3}, [%4];\n"
                 : "=r"(r0), "=r"(r1), "=r"(r2), "=r"(r3) : "r"(addr));
}
__device__ __forceinline__ void mma_bf16(float* d, const unsigned* a, const unsigned* b) {
    asm volatile(
        "mma.sync.aligned.m16n8k16.row.col.f32.bf16.bf16.f32 "
        "{%0,%1,%2,%3}, {%4,%5,%6,%7}, {%8,%9}, {%0,%1,%2,%3};\n"
        : "+f"(d[0]), "+f"(d[1]), "+f"(d[2]), "+f"(d[3])
        : "r"(a[0]), "r"(a[1]), "r"(a[2]), "r"(a[3]), "r"(b[0]), "r"(b[1]));
}

// C[n,HOUT](bf16) = A[n,K](bf16) @ W(f32->bf16); fp32 accum.
template <int K, int HOUT, bool BIASRELU, bool DISSCALE>
__global__ void __launch_bounds__(256, 2)
gemm_tc_kernel(const __nv_bfloat16* __restrict__ A,
               const float* __restrict__ W,
               const float* __restrict__ bias,
               __nv_bfloat16* __restrict__ C, int n) {
    constexpr int KC = 64;
    constexpr int SA_S = KC + 8;
    constexpr int SW_S = HOUT + 8;
    constexpr int NT = HOUT / 8;
    __shared__ __nv_bfloat16 sA[128 * SA_S];
    __shared__ __nv_bfloat16 sW[KC * SW_S];

    int tid = threadIdx.x;
    int wid = tid >> 5;
    int lane = tid & 31;
    int rowBase = blockIdx.x * 128;
    int m0 = wid * 16;

    float acc[NT][4];
#pragma unroll
    for (int t = 0; t < NT; t++)
#pragma unroll
        for (int j = 0; j < 4; j++) acc[t][j] = 0.0f;

    for (int kc = 0; kc < K; kc += KC) {
        constexpr int SEGS = KC / 8;
        for (int i = tid; i < 128 * SEGS; i += 256) {
            int r = i / SEGS, sg = i % SEGS;
            int row = rowBase + r;
            uint4 v = make_uint4(0, 0, 0, 0);
            if (row < n)
                v = *reinterpret_cast<const uint4*>(A + (size_t)row * K + kc + sg * 8);
            *reinterpret_cast<uint4*>(&sA[r * SA_S + sg * 8]) = v;
        }
        constexpr int WC4 = HOUT / 4;
        for (int i = tid; i < KC * WC4; i += 256) {
            int k = i / WC4, c4 = i % WC4;
            float4 w = *reinterpret_cast<const float4*>(W + (size_t)(kc + k) * HOUT + c4 * 4);
            __nv_bfloat162 p0 = __floats2bfloat162_rn(w.x, w.y);
            __nv_bfloat162 p1 = __floats2bfloat162_rn(w.z, w.w);
            uint2 pk;
            pk.x = *reinterpret_cast<unsigned*>(&p0);
            pk.y = *reinterpret_cast<unsigned*>(&p1);
            *reinterpret_cast<uint2*>(&sW[k * SW_S + c4 * 4]) = pk;
        }
        __syncthreads();

#pragma unroll
        for (int ks = 0; ks < KC / 16; ks++) {
            int k0 = ks * 16;
            unsigned a[4];
            {
                int r = m0 + (lane & 15);
                int c = k0 + (lane >> 4) * 8;
                ldsm_x4(a[0], a[1], a[2], a[3], smem_u32(&sA[r * SA_S + c]));
            }
#pragma unroll
            for (int nt2 = 0; nt2 < NT / 2; nt2++) {
                int n0 = nt2 * 16;
                unsigned b[4];
                int rk = k0 + (lane & 15);
                int cn = n0 + (lane >> 4) * 8;
                ldsm_x4_t(b[0], b[1], b[2], b[3], smem_u32(&sW[rk * SW_S + cn]));
                mma_bf16(acc[2 * nt2], a, b);
                mma_bf16(acc[2 * nt2 + 1], a, b + 2);
            }
        }
        __syncthreads();
    }

    int r = lane >> 2;
    int c2 = (lane & 3) * 2;
    int row0 = rowBase + m0 + r;
    int row1 = row0 + 8;
    float ds0 = 1.f, ds1 = 1.f;
    if (DISSCALE) {
        if (row0 < n) ds0 = g_dis[row0];
        if (row1 < n) ds1 = g_dis[row1];
    }
#pragma unroll
    for (int t = 0; t < NT; t++) {
        int col = t * 8 + c2;
        float v0 = acc[t][0], v1 = acc[t][1], v2 = acc[t][2], v3 = acc[t][3];
        if (BIASRELU) {
            float b0 = bias[col], b1 = bias[col + 1];
            v0 = fmaxf(v0 + b0, 0.f); v1 = fmaxf(v1 + b1, 0.f);
            v2 = fmaxf(v2 + b0, 0.f); v3 = fmaxf(v3 + b1, 0.f);
        }
        if (DISSCALE) { v0 *= ds0; v1 *= ds0; v2 *= ds1; v3 *= ds1; }
        if (row0 < n) {
            __nv_bfloat162 p = __floats2bfloat162_rn(v0, v1);
            *reinterpret_cast<unsigned*>(C + (size_t)row0 * HOUT + col) =
                *reinterpret_cast<unsigned*>(&p);
        }
        if (row1 < n) {
            __nv_bfloat162 p = __floats2bfloat162_rn(v2, v3);
            *reinterpret_cast<unsigned*>(C + (size_t)row1 * HOUT + col) =
                *reinterpret_cast<unsigned*>(&p);
        }
    }
}

// ---------------- agg, 4 nodes per warp (8 lanes each), width 64 ------------
// out = dd * (sum_{N(w)} h[s] + h[w]); uint4 per lane (8 bf16).
__global__ void agg64_kernel(const __nv_bfloat16* __restrict__ h,
                             __nv_bfloat16* __restrict__ out, int n) {
    int warp = (blockIdx.x * blockDim.x + threadIdx.x) >> 5;
    int lane = threadIdx.x & 31;
    int q  = lane >> 3;           // 0..3
    int ql = lane & 7;            // lane within quarter
    int w = warp * 4 + q;
    bool valid = w < n;

    int beg = 0, end = 0;
    float dd = 0.f;
    if (valid) {
        beg = (w == 0) ? 0 : g_off[w - 1];
        end = g_off[w];
        dd  = g_dis[w];
    }

    float4 aL0 = make_float4(0.f, 0.f, 0.f, 0.f), aH0 = aL0;
    float4 aL1 = aL0, aH1 = aL0;
#define ACCU4(AL, AH, U) { \
        float2 t0 = __bfloat1622float2(u2bf2((U).x)); \
        float2 t1 = __bfloat1622float2(u2bf2((U).y)); \
        float2 t2 = __bfloat1622float2(u2bf2((U).z)); \
        float2 t3 = __bfloat1622float2(u2bf2((U).w)); \
        AL.x += t0.x; AL.y += t0.y; AL.z += t1.x; AL.w += t1.y; \
        AH.x += t2.x; AH.y += t2.y; AH.z += t3.x; AH.w += t3.y; }
    int i = beg;
    for (; i + 2 <= end; i += 2) {
        int s0 = g_col[i], s1 = g_col[i + 1];
        uint4 u0 = reinterpret_cast<const uint4*>(h + (size_t)s0 * 64)[ql];
        uint4 u1 = reinterpret_cast<const uint4*>(h + (size_t)s1 * 64)[ql];
        ACCU4(aL0, aH0, u0)
        ACCU4(aL1, aH1, u1)
    }
    if (i < end) {
        uint4 u0 = reinterpret_cast<const uint4*>(h + (size_t)g_col[i] * 64)[ql];
        ACCU4(aL0, aH0, u0)
    }
    if (valid) {
        uint4 us = reinterpret_cast<const uint4*>(h + (size_t)w * 64)[ql];
        ACCU4(aL0, aH0, us)
        float o0 = dd * (aL0.x + aL1.x), o1 = dd * (aL0.y + aL1.y);
        float o2 = dd * (aL0.z + aL1.z), o3 = dd * (aL0.w + aL1.w);
        float o4 = dd * (aH0.x + aH1.x), o5 = dd * (aH0.y + aH1.y);
        float o6 = dd * (aH0.z + aH1.z), o7 = dd * (aH0.w + aH1.w);
        __nv_bfloat162 r0 = __floats2bfloat162_rn(o0, o1);
        __nv_bfloat162 r1 = __floats2bfloat162_rn(o2, o3);
        __nv_bfloat162 r2 = __floats2bfloat162_rn(o4, o5);
        __nv_bfloat162 r3 = __floats2bfloat162_rn(o6, o7);
        uint4 r;
        r.x = *reinterpret_cast<unsigned*>(&r0);
        r.y = *reinterpret_cast<unsigned*>(&r1);
        r.z = *reinterpret_cast<unsigned*>(&r2);
        r.w = *reinterpret_cast<unsigned*>(&r3);
        reinterpret_cast<uint4*>(out + (size_t)w * 64)[ql] = r;
    }
}

// ---------------- agg, 2 nodes per warp, width 128, unroll 4 ----------------
__global__ void agg128_kernel(const __nv_bfloat16* __restrict__ h,
                              const float* __restrict__ bias,
                              __nv_bfloat16* __restrict__ out, int n) {
    int warp = (blockIdx.x * blockDim.x + threadIdx.x) >> 5;
    int lane = threadIdx.x & 31;
    int half = lane >> 4;
    int hl   = lane & 15;
    int w = warp * 2 + half;
    bool valid = w < n;

    int beg = 0, end = 0;
    float dd = 0.f;
    if (valid) {
        beg = (w == 0) ? 0 : g_off[w - 1];
        end = g_off[w];
        dd  = g_dis[w];
    }

    float4 aL0 = make_float4(0.f, 0.f, 0.f, 0.f), aH0 = aL0;
    float4 aL1 = aL0, aH1 = aL0;
    int i = beg;
    for (; i + 4 <= end; i += 4) {
        int s0 = g_col[i], s1 = g_col[i + 1], s2 = g_col[i + 2], s3 = g_col[i + 3];
        uint4 u0 = reinterpret_cast<const uint4*>(h + (size_t)s0 * 128)[hl];
        uint4 u1 = reinterpret_cast<const uint4*>(h + (size_t)s1 * 128)[hl];
        uint4 u2 = reinterpret_cast<const uint4*>(h + (size_t)s2 * 128)[hl];
        uint4 u3 = reinterpret_cast<const uint4*>(h + (size_t)s3 * 128)[hl];
        ACCU4(aL0, aH0, u0)
        ACCU4(aL1, aH1, u1)
        ACCU4(aL0, aH0, u2)
        ACCU4(aL1, aH1, u3)
    }
    for (; i < end; i++) {
        uint4 u0 = reinterpret_cast<const uint4*>(h + (size_t)g_col[i] * 128)[hl];
        ACCU4(aL0, aH0, u0)
    }
    if (valid) {
        uint4 us = reinterpret_cast<const uint4*>(h + (size_t)w * 128)[hl];
        ACCU4(aL0, aH0, us)

        float4 bb0 = reinterpret_cast<const float4*>(bias)[hl * 2];
        float4 bb1 = reinterpret_cast<const float4*>(bias)[hl * 2 + 1];
        float o0 = fmaxf(dd * (aL0.x + aL1.x) + bb0.x, 0.f) * dd;
        float o1 = fmaxf(dd * (aL0.y + aL1.y) + bb0.y, 0.f) * dd;
        float o2 = fmaxf(dd * (aL0.z + aL1.z) + bb0.z, 0.f) * dd;
        float o3 = fmaxf(dd * (aL0.w + aL1.w) + bb0.w, 0.f) * dd;
        float o4 = fmaxf(dd * (aH0.x + aH1.x) + bb1.x, 0.f) * dd;
        float o5 = fmaxf(dd * (aH0.y + aH1.y) + bb1.y, 0.f) * dd;
        float o6 = fmaxf(dd * (aH0.z + aH1.z) + bb1.z, 0.f) * dd;
        float o7 = fmaxf(dd * (aH0.w + aH1.w) + bb1.w, 0.f) * dd;
        __nv_bfloat162 r0 = __floats2bfloat162_rn(o0, o1);
        __nv_bfloat162 r1 = __floats2bfloat162_rn(o2, o3);
        __nv_bfloat162 r2 = __floats2bfloat162_rn(o4, o5);
        __nv_bfloat162 r3 = __floats2bfloat162_rn(o6, o7);
        uint4 r;
        r.x = *reinterpret_cast<unsigned*>(&r0);
        r.y = *reinterpret_cast<unsigned*>(&r1);
        r.z = *reinterpret_cast<unsigned*>(&r2);
        r.w = *reinterpret_cast<unsigned*>(&r3);
        reinterpret_cast<uint4*>(out + (size_t)w * 128)[hl] = r;
    }
}

// ---------------- layer-3 agg (4 nodes/warp, width 64) + mean pool ----------
__global__ void agg_pool_kernel(const __nv_bfloat16* __restrict__ h,
                                const float* __restrict__ bias, int n) {
    __shared__ float sp[64];
    int tid = threadIdx.x;
    if (tid < 64) sp[tid] = 0.f;
    __syncthreads();

    int warp = (blockIdx.x * blockDim.x + tid) >> 5;
    int lane = tid & 31;
    int q  = lane >> 3;
    int ql = lane & 7;
    int w = warp * 4 + q;
    bool valid = w < n;

    int beg = 0, end = 0;
    float dd = 0.f;
    if (valid) {
        beg = (w == 0) ? 0 : g_off[w - 1];
        end = g_off[w];
        dd  = g_dis[w];
    }

    float4 aL0 = make_float4(0.f, 0.f, 0.f, 0.f), aH0 = aL0;
    float4 aL1 = aL0, aH1 = aL0;
    int i = beg;
    for (; i + 2 <= end; i += 2) {
        int s0 = g_col[i], s1 = g_col[i + 1];
        uint4 u0 = reinterpret_cast<const uint4*>(h + (size_t)s0 * 64)[ql];
        uint4 u1 = reinterpret_cast<const uint4*>(h + (size_t)s1 * 64)[ql];
        ACCU4(aL0, aH0, u0)
        ACCU4(aL1, aH1, u1)
    }
    if (i < end) {
        uint4 u0 = reinterpret_cast<const uint4*>(h + (size_t)g_col[i] * 64)[ql];
        ACCU4(aL0, aH0, u0)
    }
    if (valid) {
        uint4 us = reinterpret_cast<const uint4*>(h + (size_t)w * 64)[ql];
        ACCU4(aL0, aH0, us)

        float4 bb0 = reinterpret_cast<const float4*>(bias)[ql * 2];
        float4 bb1 = reinterpret_cast<const float4*>(bias)[ql * 2 + 1];
        float o0 = fmaxf(dd * (aL0.x + aL1.x) + bb0.x, 0.f);
        float o1 = fmaxf(dd * (aL0.y + aL1.y) + bb0.y, 0.f);
        float o2 = fmaxf(dd * (aL0.z + aL1.z) + bb0.z, 0.f);
        float o3 = fmaxf(dd * (aL0.w + aL1.w) + bb0.w, 0.f);
        float o4 = fmaxf(dd * (aH0.x + aH1.x) + bb1.x, 0.f);
        float o5 = fmaxf(dd * (aH0.y + aH1.y) + bb1.y, 0.f);
        float o6 = fmaxf(dd * (aH0.z + aH1.z) + bb1.z, 0.f);
        float o7 = fmaxf(dd * (aH0.w + aH1.w) + bb1.w, 0.f);
        atomicAdd(&sp[ql * 8 + 0], o0);
        atomicAdd(&sp[ql * 8 + 1], o1);
        atomicAdd(&sp[ql * 8 + 2], o2);
        atomicAdd(&sp[ql * 8 + 3], o3);
        atomicAdd(&sp[ql * 8 + 4], o4);
        atomicAdd(&sp[ql * 8 + 5], o5);
        atomicAdd(&sp[ql * 8 + 6], o6);
        atomicAdd(&sp[ql * 8 + 7], o7);
    }
    __syncthreads();
    if (tid < 64) atomicAdd(&g_pooled[tid], sp[tid]);
#undef ACCU4
}

// ---------------- classifier + softmax --------------------------------------
__global__ void cls_kernel(const float* __restrict__ Wc1, const float* __restrict__ bc1,
                           const float* __restrict__ Wc2, const float* __restrict__ bc2,
                           float* __restrict__ out, float invN) {
    __shared__ float z[32];
    int t = threadIdx.x;
    if (t < 32) {
        float a = bc1[t];
        for (int i = 0; i < 64; i++)
            a = fmaf(g_pooled[i] * invN, Wc1[i * 32 + t], a);
        z[t] = fmaxf(a, 0.f);
    }
    __syncthreads();
    if (t == 0) {
        float l0 = bc2[0], l1 = bc2[1];
        for (int j = 0; j < 32; j++) {
            l0 = fmaf(z[j], Wc2[j * 2 + 0], l0);
            l1 = fmaf(z[j], Wc2[j * 2 + 1], l1);
        }
        float m = fmaxf(l0, l1);
        float e0 = expf(l0 - m), e1 = expf(l1 - m);
        float s = e0 + e1;
        out[0] = e0 / s;
        out[1] = e1 / s;
    }
}

// ---------------- launch -----------------------------------------------------
extern "C" void kernel_launch(void* const* d_in, const int* in_sizes, int n_in,
                              void* d_out, int out_size) {
    const float* x   = (const float*)d_in[0];
    const int*   ei  = (const int*)d_in[1];
    const float* W1  = (const float*)d_in[2];
    const float* b1  = (const float*)d_in[3];
    const float* W2  = (const float*)d_in[4];
    const float* b2  = (const float*)d_in[5];
    const float* W3  = (const float*)d_in[6];
    const float* b3  = (const float*)d_in[7];
    const float* Wc1 = (const float*)d_in[8];
    const float* bc1 = (const float*)d_in[9];
    const float* Wc2 = (const float*)d_in[10];
    const float* bc2 = (const float*)d_in[11];
    float* out = (float*)d_out;

    int n = in_sizes[0] / 64;
    int e = in_sizes[1] / 2;
    const int* src = ei;
    const int* dst = ei + e;
    int nb = (n + SCAN_CHUNK - 1) / SCAN_CHUNK;

    __nv_bfloat16* A;  cudaGetSymbolAddress((void**)&A, g_hA);
    __nv_bfloat16* B;  cudaGetSymbolAddress((void**)&B, g_hB);

    // graph prep
    zero_kernel<<<512, 256>>>(n);
    degree_kernel<<<1024, 256>>>(dst, e);
    scanA_kernel<<<nb, 256>>>(n);                 // deg sums + dis
    cvt_kernel<<<1024, 256>>>(x, A, n * 8);       // x -> dis-prescaled bf16 (T0)
    scanC_kernel<<<nb, 256>>>(nb, n);             // offsets
    fill_kernel<<<1024, 256>>>(src, dst, e);      // CSR (in-place cursors)

    int gg = (n + 127) / 128;
    int ga2 = (n + 15) / 16;  // 2 nodes/warp, 8 warps/block
    int ga4 = (n + 31) / 32;  // 4 nodes/warp, 8 warps/block
    // layer 1: agg(T0) -> unscaled a ; gemm1: relu(a@W1+b1)*dis -> T1 (prescaled)
    agg64_kernel<<<ga4, 256>>>(A, B, n);
    gemm_tc_kernel<64, 128, true, true><<<gg, 256>>>(B, W1, b1, A, n);
    // layer 2: gemm2(T1@W2) = messages ; agg2: relu(dd*sum+b2)*dd -> T2 (prescaled)
    gemm_tc_kernel<128, 128, false, false><<<gg, 256>>>(A, W2, nullptr, B, n);
    agg128_kernel<<<ga2, 256>>>(B, b2, A, n);
    // layer 3: gemm3(T2@W3) = messages ; agg+pool
    gemm_tc_kernel<128, 64, false, false><<<gg, 256>>>(A, W3, nullptr, B, n);
    agg_pool_kernel<<<ga4, 256>>>(B, b3, n);

    cls_kernel<<<1, 64>>>(Wc1, bc1, Wc2, bc2, out, 1.0f / (float)n);
}

// round 14
// speedup vs baseline: 1.0060x; 1.0060x over previous
#include <cuda_runtime.h>
#include <cuda_bf16.h>
#include <math.h>

#define MAXN 100000
#define MAXE 1600000
#define SCAN_CHUNK 1024

// ---------------- scratch ---------------------------------------------------
__device__ __align__(16) int   g_edeg[MAXN];
__device__ __align__(16) float g_dis[MAXN];
__device__ __align__(16) int   g_off[MAXN + 1];   // after fill: inclusive ends
__device__ __align__(16) int   g_col[MAXE];
__device__ __align__(16) int   g_bsum[128];
__device__ __align__(16) __nv_bfloat16 g_hA[(size_t)MAXN * 128];
__device__ __align__(16) __nv_bfloat16 g_hB[(size_t)MAXN * 128];
__device__ __align__(16) float g_pooled[64];

__device__ __forceinline__ __nv_bfloat162 u2bf2(unsigned u) {
    return *reinterpret_cast<__nv_bfloat162*>(&u);
}

// ---------------- zero scratch ----------------------------------------------
__global__ void zero_kernel(int n) {
    int i = blockIdx.x * blockDim.x + threadIdx.x;
    int stride = gridDim.x * blockDim.x;
    for (int k = i; k < n; k += stride) g_edeg[k] = 0;
    if (i < 64) g_pooled[i] = 0.0f;
}

// ---------------- degree histogram over dst (int4 vectorized) ---------------
__global__ void degree_kernel(const int* __restrict__ dst, int e) {
    int i = blockIdx.x * blockDim.x + threadIdx.x;
    int stride = gridDim.x * blockDim.x;
    int e4 = e >> 2;
    for (int k = i; k < e4; k += stride) {
        int4 d = reinterpret_cast<const int4*>(dst)[k];
        atomicAdd(&g_edeg[d.x], 1);
        atomicAdd(&g_edeg[d.y], 1);
        atomicAdd(&g_edeg[d.z], 1);
        atomicAdd(&g_edeg[d.w], 1);
    }
    if (i < (e & 3)) atomicAdd(&g_edeg[dst[e4 * 4 + i]], 1);
}

// ---------------- scan phase A: per-block sums + dis ------------------------
__global__ void scanA_kernel(int n) {
    __shared__ int ssum[8];
    int base = blockIdx.x * SCAN_CHUNK + threadIdx.x * 4;
    int s = 0;
#pragma unroll
    for (int j = 0; j < 4; j++) {
        int idx = base + j;
        if (idx < n) {
            int d = g_edeg[idx];
            s += d;
            g_dis[idx] = rsqrtf((float)(d + 1));
        }
    }
#pragma unroll
    for (int o = 16; o > 0; o >>= 1) s += __shfl_down_sync(0xffffffffu, s, o);
    if ((threadIdx.x & 31) == 0) ssum[threadIdx.x >> 5] = s;
    __syncthreads();
    if (threadIdx.x == 0) {
        int t = 0;
#pragma unroll
        for (int w = 0; w < 8; w++) t += ssum[w];
        g_bsum[blockIdx.x] = t;
    }
}

// ---------------- x -> bf16, prescaled by dis[row] (vectorized x8) ----------
__global__ void cvt_kernel(const float* __restrict__ x, __nv_bfloat16* __restrict__ o,
                           int total8) {
    int i = blockIdx.x * blockDim.x + threadIdx.x;
    int stride = gridDim.x * blockDim.x;
    for (int k = i; k < total8; k += stride) {
        int base = k * 8;
        float dd = g_dis[base >> 6];
        float4 a = *reinterpret_cast<const float4*>(x + base);
        float4 b = *reinterpret_cast<const float4*>(x + base + 4);
        __nv_bfloat162 p0 = __floats2bfloat162_rn(a.x * dd, a.y * dd);
        __nv_bfloat162 p1 = __floats2bfloat162_rn(a.z * dd, a.w * dd);
        __nv_bfloat162 p2 = __floats2bfloat162_rn(b.x * dd, b.y * dd);
        __nv_bfloat162 p3 = __floats2bfloat162_rn(b.z * dd, b.w * dd);
        uint4 r;
        r.x = *reinterpret_cast<unsigned*>(&p0);
        r.y = *reinterpret_cast<unsigned*>(&p1);
        r.z = *reinterpret_cast<unsigned*>(&p2);
        r.w = *reinterpret_cast<unsigned*>(&p3);
        *reinterpret_cast<uint4*>(o + base) = r;
    }
}

// ---------------- scan phase C (with inline block-sum scan) -----------------
__global__ void scanC_kernel(int nb, int n) {
    __shared__ int sb[128];
    __shared__ int sh[256];
    int t = threadIdx.x;
    if (t < 128) sb[t] = (t < nb) ? g_bsum[t] : 0;
    __syncthreads();
#pragma unroll
    for (int o = 1; o < 128; o <<= 1) {
        int u = (t >= o && t < 128) ? sb[t - o] : 0;
        __syncthreads();
        if (t < 128) sb[t] += u;
        __syncthreads();
    }
    int boff = (blockIdx.x == 0) ? 0 : sb[blockIdx.x - 1];
    if (blockIdx.x == 0 && t == 0) g_off[n] = sb[127];

    int base = blockIdx.x * SCAN_CHUNK + t * 4;
    int d[4];
    int s = 0;
#pragma unroll
    for (int j = 0; j < 4; j++) {
        int idx = base + j;
        d[j] = (idx < n) ? g_edeg[idx] : 0;
        s += d[j];
    }
    sh[t] = s;
    __syncthreads();
#pragma unroll
    for (int o = 1; o < 256; o <<= 1) {
        int u = (t >= o) ? sh[t - o] : 0;
        __syncthreads();
        sh[t] += u;
        __syncthreads();
    }
    int run = boff + sh[t] - s;
#pragma unroll
    for (int j = 0; j < 4; j++) {
        int idx = base + j;
        if (idx < n) g_off[idx] = run;
        run += d[j];
    }
}

// ---------------- CSR fill (in-place cursor on g_off, int4 vectorized) ------
__global__ void fill_kernel(const int* __restrict__ src,
                            const int* __restrict__ dst, int e) {
    int i = blockIdx.x * blockDim.x + threadIdx.x;
    int stride = gridDim.x * blockDim.x;
    int e4 = e >> 2;
    for (int k = i; k < e4; k += stride) {
        int4 d = reinterpret_cast<const int4*>(dst)[k];
        int4 s = reinterpret_cast<const int4*>(src)[k];
        g_col[atomicAdd(&g_off[d.x], 1)] = s.x;
        g_col[atomicAdd(&g_off[d.y], 1)] = s.y;
        g_col[atomicAdd(&g_off[d.z], 1)] = s.z;
        g_col[atomicAdd(&g_off[d.w], 1)] = s.w;
    }
    if (i < (e & 3)) {
        int k = e4 * 4 + i;
        g_col[atomicAdd(&g_off[dst[k]], 1)] = src[k];
    }
}

// ---------------- tensor-core GEMM ------------------------------------------
__device__ __forceinline__ unsigned smem_u32(const void* p) {
    return (unsigned)__cvta_generic_to_shared(p);
}
__device__ __forceinline__ void ldsm_x4(unsigned& r0, unsigned& r1, unsigned& r2,
                                        unsigned& r3, unsigned addr) {
    asm volatile("ldmatrix.sync.aligned.m8n8.x4.shared.b16 {%0,%1,%2,%3}, [%4];\n"
                 : "=r"(r0), "=r"(r1), "=r"(r2), "=r"(r3) : "r"(addr));
}
__device__ __forceinline__ void ldsm_x4_t(unsigned& r0, unsigned& r1, unsigned& r2,
                                          unsigned& r3, unsigned addr) {
    asm volatile("ldmatrix.sync.aligned.m8n8.x4.trans.shared.b16 {%0,%1,%2,%3}, [%4];\n"
                 : "=r"(r0), "=r"(r1), "=r"(r2), "=r"(r3) : "r"(addr));
}
__device__ __forceinline__ void mma_bf16(float* d, const unsigned* a, const unsigned* b) {
    asm volatile(
        "mma.sync.aligned.m16n8k16.row.col.f32.bf16.bf16.f32 "
        "{%0,%1,%2,%3}, {%4,%5,%6,%7}, {%8,%9}, {%0,%1,%2,%3};\n"
        : "+f"(d[0]), "+f"(d[1]), "+f"(d[2]), "+f"(d[3])
        : "r"(a[0]), "r"(a[1]), "r"(a[2]), "r"(a[3]), "r"(b[0]), "r"(b[1]));
}

// C[n,HOUT](bf16) = A[n,K](bf16) @ W(f32->bf16); fp32 accum.
template <int K, int HOUT, bool BIASRELU, bool DISSCALE>
__global__ void __launch_bounds__(256, 2)
gemm_tc_kernel(const __nv_bfloat16* __restrict__ A,
               const float* __restrict__ W,
               const float* __restrict__ bias,
               __nv_bfloat16* __restrict__ C, int n) {
    constexpr int KC = 64;
    constexpr int SA_S = KC + 8;
    constexpr int SW_S = HOUT + 8;
    constexpr int NT = HOUT / 8;
    __shared__ __nv_bfloat16 sA[128 * SA_S];
    __shared__ __nv_bfloat16 sW[KC * SW_S];

    int tid = threadIdx.x;
    int wid = tid >> 5;
    int lane = tid & 31;
    int rowBase = blockIdx.x * 128;
    int m0 = wid * 16;

    float acc[NT][4];
#pragma unroll
    for (int t = 0; t < NT; t++)
#pragma unroll
        for (int j = 0; j < 4; j++) acc[t][j] = 0.0f;

    for (int kc = 0; kc < K; kc += KC) {
        constexpr int SEGS = KC / 8;
        for (int i = tid; i < 128 * SEGS; i += 256) {
            int r = i / SEGS, sg = i % SEGS;
            int row = rowBase + r;
            uint4 v = make_uint4(0, 0, 0, 0);
            if (row < n)
                v = *reinterpret_cast<const uint4*>(A + (size_t)row * K + kc + sg * 8);
            *reinterpret_cast<uint4*>(&sA[r * SA_S + sg * 8]) = v;
        }
        constexpr int WC4 = HOUT / 4;
        for (int i = tid; i < KC * WC4; i += 256) {
            int k = i / WC4, c4 = i % WC4;
            float4 w = *reinterpret_cast<const float4*>(W + (size_t)(kc + k) * HOUT + c4 * 4);
            __nv_bfloat162 p0 = __floats2bfloat162_rn(w.x, w.y);
            __nv_bfloat162 p1 = __floats2bfloat162_rn(w.z, w.w);
            uint2 pk;
            pk.x = *reinterpret_cast<unsigned*>(&p0);
            pk.y = *reinterpret_cast<unsigned*>(&p1);
            *reinterpret_cast<uint2*>(&sW[k * SW_S + c4 * 4]) = pk;
        }
        __syncthreads();

#pragma unroll
        for (int ks = 0; ks < KC / 16; ks++) {
            int k0 = ks * 16;
            unsigned a[4];
            {
                int r = m0 + (lane & 15);
                int c = k0 + (lane >> 4) * 8;
                ldsm_x4(a[0], a[1], a[2], a[3], smem_u32(&sA[r * SA_S + c]));
            }
#pragma unroll
            for (int nt2 = 0; nt2 < NT / 2; nt2++) {
                int n0 = nt2 * 16;
                unsigned b[4];
                int rk = k0 + (lane & 15);
                int cn = n0 + (lane >> 4) * 8;
                ldsm_x4_t(b[0], b[1], b[2], b[3], smem_u32(&sW[rk * SW_S + cn]));
                mma_bf16(acc[2 * nt2], a, b);
                mma_bf16(acc[2 * nt2 + 1], a, b + 2);
            }
        }
        __syncthreads();
    }

    int r = lane >> 2;
    int c2 = (lane & 3) * 2;
    int row0 = rowBase + m0 + r;
    int row1 = row0 + 8;
    float ds0 = 1.f, ds1 = 1.f;
    if (DISSCALE) {
        if (row0 < n) ds0 = g_dis[row0];
        if (row1 < n) ds1 = g_dis[row1];
    }
#pragma unroll
    for (int t = 0; t < NT; t++) {
        int col = t * 8 + c2;
        float v0 = acc[t][0], v1 = acc[t][1], v2 = acc[t][2], v3 = acc[t][3];
        if (BIASRELU) {
            float b0 = bias[col], b1 = bias[col + 1];
            v0 = fmaxf(v0 + b0, 0.f); v1 = fmaxf(v1 + b1, 0.f);
            v2 = fmaxf(v2 + b0, 0.f); v3 = fmaxf(v3 + b1, 0.f);
        }
        if (DISSCALE) { v0 *= ds0; v1 *= ds0; v2 *= ds1; v3 *= ds1; }
        if (row0 < n) {
            __nv_bfloat162 p = __floats2bfloat162_rn(v0, v1);
            *reinterpret_cast<unsigned*>(C + (size_t)row0 * HOUT + col) =
                *reinterpret_cast<unsigned*>(&p);
        }
        if (row1 < n) {
            __nv_bfloat162 p = __floats2bfloat162_rn(v2, v3);
            *reinterpret_cast<unsigned*>(C + (size_t)row1 * HOUT + col) =
                *reinterpret_cast<unsigned*>(&p);
        }
    }
}

// ---------------- agg, 2 nodes per warp (16 lanes each), width 64 -----------
// out = dd * (sum_{N(w)} h[s] + h[w]); uint2 per lane (4 bf16).
__global__ void agg64_kernel(const __nv_bfloat16* __restrict__ h,
                             __nv_bfloat16* __restrict__ out, int n) {
    int warp = (blockIdx.x * blockDim.x + threadIdx.x) >> 5;
    int lane = threadIdx.x & 31;
    int half = lane >> 4;          // 0 or 1
    int hl   = lane & 15;          // lane within half
    int w = warp * 2 + half;       // node
    bool valid = w < n;

    int beg = 0, end = 0;
    float dd = 0.f;
    if (valid) {
        beg = (w == 0) ? 0 : g_off[w - 1];
        end = g_off[w];
        dd  = g_dis[w];
    }

    float4 a0 = make_float4(0.f, 0.f, 0.f, 0.f);
    float4 a1 = make_float4(0.f, 0.f, 0.f, 0.f);
    int i = beg;
    for (; i + 2 <= end; i += 2) {
        int s0 = g_col[i], s1 = g_col[i + 1];
        uint2 u0 = reinterpret_cast<const uint2*>(h + (size_t)s0 * 64)[hl];
        uint2 u1 = reinterpret_cast<const uint2*>(h + (size_t)s1 * 64)[hl];
        float2 p0 = __bfloat1622float2(u2bf2(u0.x));
        float2 p1 = __bfloat1622float2(u2bf2(u0.y));
        float2 q0 = __bfloat1622float2(u2bf2(u1.x));
        float2 q1 = __bfloat1622float2(u2bf2(u1.y));
        a0.x += p0.x; a0.y += p0.y; a0.z += p1.x; a0.w += p1.y;
        a1.x += q0.x; a1.y += q0.y; a1.z += q1.x; a1.w += q1.y;
    }
    if (i < end) {
        int s0 = g_col[i];
        uint2 u0 = reinterpret_cast<const uint2*>(h + (size_t)s0 * 64)[hl];
        float2 p0 = __bfloat1622float2(u2bf2(u0.x));
        float2 p1 = __bfloat1622float2(u2bf2(u0.y));
        a0.x += p0.x; a0.y += p0.y; a0.z += p1.x; a0.w += p1.y;
    }
    if (valid) {
        uint2 us = reinterpret_cast<const uint2*>(h + (size_t)w * 64)[hl];
        float2 p0 = __bfloat1622float2(u2bf2(us.x));
        float2 p1 = __bfloat1622float2(u2bf2(us.y));
        a0.x += p0.x; a0.y += p0.y; a0.z += p1.x; a0.w += p1.y;

        float ox = dd * (a0.x + a1.x), oy = dd * (a0.y + a1.y);
        float oz = dd * (a0.z + a1.z), ow = dd * (a0.w + a1.w);
        __nv_bfloat162 r0 = __floats2bfloat162_rn(ox, oy);
        __nv_bfloat162 r1 = __floats2bfloat162_rn(oz, ow);
        uint2 r;
        r.x = *reinterpret_cast<unsigned*>(&r0);
        r.y = *reinterpret_cast<unsigned*>(&r1);
        reinterpret_cast<uint2*>(out + (size_t)w * 64)[hl] = r;
    }
}

// ---------------- agg layer 2: feature-split (gridDim.y=2), 2 nodes/warp ----
// Each block handles 64 of the 128 features (blockIdx.y selects half).
// Twice the resident warps walk the edge lists -> 2x outstanding gathers.
__global__ void agg128_split_kernel(const __nv_bfloat16* __restrict__ h,
                                    const float* __restrict__ bias,
                                    __nv_bfloat16* __restrict__ out, int n) {
    int warp = (blockIdx.x * blockDim.x + threadIdx.x) >> 5;
    int lane = threadIdx.x & 31;
    int half = lane >> 4;
    int hl   = lane & 15;
    int w = warp * 2 + half;
    int foff = blockIdx.y * 64;     // feature offset of this half
    bool valid = w < n;

    int beg = 0, end = 0;
    float dd = 0.f;
    if (valid) {
        beg = (w == 0) ? 0 : g_off[w - 1];
        end = g_off[w];
        dd  = g_dis[w];
    }

    const __nv_bfloat16* hb = h + foff;
    float4 a0 = make_float4(0.f, 0.f, 0.f, 0.f);
    float4 a1 = make_float4(0.f, 0.f, 0.f, 0.f);
    int i = beg;
    for (; i + 2 <= end; i += 2) {
        int s0 = g_col[i], s1 = g_col[i + 1];
        uint2 u0 = reinterpret_cast<const uint2*>(hb + (size_t)s0 * 128)[hl];
        uint2 u1 = reinterpret_cast<const uint2*>(hb + (size_t)s1 * 128)[hl];
        float2 p0 = __bfloat1622float2(u2bf2(u0.x));
        float2 p1 = __bfloat1622float2(u2bf2(u0.y));
        float2 q0 = __bfloat1622float2(u2bf2(u1.x));
        float2 q1 = __bfloat1622float2(u2bf2(u1.y));
        a0.x += p0.x; a0.y += p0.y; a0.z += p1.x; a0.w += p1.y;
        a1.x += q0.x; a1.y += q0.y; a1.z += q1.x; a1.w += q1.y;
    }
    if (i < end) {
        int s0 = g_col[i];
        uint2 u0 = reinterpret_cast<const uint2*>(hb + (size_t)s0 * 128)[hl];
        float2 p0 = __bfloat1622float2(u2bf2(u0.x));
        float2 p1 = __bfloat1622float2(u2bf2(u0.y));
        a0.x += p0.x; a0.y += p0.y; a0.z += p1.x; a0.w += p1.y;
    }
    if (valid) {
        uint2 us = reinterpret_cast<const uint2*>(hb + (size_t)w * 128)[hl];
        float2 p0 = __bfloat1622float2(u2bf2(us.x));
        float2 p1 = __bfloat1622float2(u2bf2(us.y));
        a0.x += p0.x; a0.y += p0.y; a0.z += p1.x; a0.w += p1.y;

        float4 bb = reinterpret_cast<const float4*>(bias + foff)[hl];
        float o0 = fmaxf(dd * (a0.x + a1.x) + bb.x, 0.f) * dd;
        float o1 = fmaxf(dd * (a0.y + a1.y) + bb.y, 0.f) * dd;
        float o2 = fmaxf(dd * (a0.z + a1.z) + bb.z, 0.f) * dd;
        float o3 = fmaxf(dd * (a0.w + a1.w) + bb.w, 0.f) * dd;
        __nv_bfloat162 r0 = __floats2bfloat162_rn(o0, o1);
        __nv_bfloat162 r1 = __floats2bfloat162_rn(o2, o3);
        uint2 r;
        r.x = *reinterpret_cast<unsigned*>(&r0);
        r.y = *reinterpret_cast<unsigned*>(&r1);
        reinterpret_cast<uint2*>(out + (size_t)w * 128 + foff)[hl] = r;
    }
}

// ---------------- layer-3 agg (2 nodes/warp, width 64) + mean pool ----------
__global__ void agg_pool_kernel(const __nv_bfloat16* __restrict__ h,
                                const float* __restrict__ bias, int n) {
    __shared__ float sp[64];
    int tid = threadIdx.x;
    if (tid < 64) sp[tid] = 0.f;
    __syncthreads();

    int warp = (blockIdx.x * blockDim.x + tid) >> 5;
    int lane = tid & 31;
    int half = lane >> 4;
    int hl   = lane & 15;
    int w = warp * 2 + half;
    bool valid = w < n;

    int beg = 0, end = 0;
    float dd = 0.f;
    if (valid) {
        beg = (w == 0) ? 0 : g_off[w - 1];
        end = g_off[w];
        dd  = g_dis[w];
    }

    float4 a0 = make_float4(0.f, 0.f, 0.f, 0.f);
    float4 a1 = make_float4(0.f, 0.f, 0.f, 0.f);
    int i = beg;
    for (; i + 2 <= end; i += 2) {
        int s0 = g_col[i], s1 = g_col[i + 1];
        uint2 u0 = reinterpret_cast<const uint2*>(h + (size_t)s0 * 64)[hl];
        uint2 u1 = reinterpret_cast<const uint2*>(h + (size_t)s1 * 64)[hl];
        float2 p0 = __bfloat1622float2(u2bf2(u0.x));
        float2 p1 = __bfloat1622float2(u2bf2(u0.y));
        float2 q0 = __bfloat1622float2(u2bf2(u1.x));
        float2 q1 = __bfloat1622float2(u2bf2(u1.y));
        a0.x += p0.x; a0.y += p0.y; a0.z += p1.x; a0.w += p1.y;
        a1.x += q0.x; a1.y += q0.y; a1.z += q1.x; a1.w += q1.y;
    }
    if (i < end) {
        int s0 = g_col[i];
        uint2 u0 = reinterpret_cast<const uint2*>(h + (size_t)s0 * 64)[hl];
        float2 p0 = __bfloat1622float2(u2bf2(u0.x));
        float2 p1 = __bfloat1622float2(u2bf2(u0.y));
        a0.x += p0.x; a0.y += p0.y; a0.z += p1.x; a0.w += p1.y;
    }
    if (valid) {
        uint2 us = reinterpret_cast<const uint2*>(h + (size_t)w * 64)[hl];
        float2 p0 = __bfloat1622float2(u2bf2(us.x));
        float2 p1 = __bfloat1622float2(u2bf2(us.y));
        a0.x += p0.x; a0.y += p0.y; a0.z += p1.x; a0.w += p1.y;

        float4 bb = reinterpret_cast<const float4*>(bias)[hl];
        float o0 = fmaxf(dd * (a0.x + a1.x) + bb.x, 0.f);
        float o1 = fmaxf(dd * (a0.y + a1.y) + bb.y, 0.f);
        float o2 = fmaxf(dd * (a0.z + a1.z) + bb.z, 0.f);
        float o3 = fmaxf(dd * (a0.w + a1.w) + bb.w, 0.f);
        atomicAdd(&sp[hl * 4 + 0], o0);
        atomicAdd(&sp[hl * 4 + 1], o1);
        atomicAdd(&sp[hl * 4 + 2], o2);
        atomicAdd(&sp[hl * 4 + 3], o3);
    }
    __syncthreads();
    if (tid < 64) atomicAdd(&g_pooled[tid], sp[tid]);
}

// ---------------- classifier + softmax --------------------------------------
__global__ void cls_kernel(const float* __restrict__ Wc1, const float* __restrict__ bc1,
                           const float* __restrict__ Wc2, const float* __restrict__ bc2,
                           float* __restrict__ out, float invN) {
    __shared__ float z[32];
    int t = threadIdx.x;
    if (t < 32) {
        float a = bc1[t];
        for (int i = 0; i < 64; i++)
            a = fmaf(g_pooled[i] * invN, Wc1[i * 32 + t], a);
        z[t] = fmaxf(a, 0.f);
    }
    __syncthreads();
    if (t == 0) {
        float l0 = bc2[0], l1 = bc2[1];
        for (int j = 0; j < 32; j++) {
            l0 = fmaf(z[j], Wc2[j * 2 + 0], l0);
            l1 = fmaf(z[j], Wc2[j * 2 + 1], l1);
        }
        float m = fmaxf(l0, l1);
        float e0 = expf(l0 - m), e1 = expf(l1 - m);
        float s = e0 + e1;
        out[0] = e0 / s;
        out[1] = e1 / s;
    }
}

// ---------------- launch -----------------------------------------------------
extern "C" void kernel_launch(void* const* d_in, const int* in_sizes, int n_in,
                              void* d_out, int out_size) {
    const float* x   = (const float*)d_in[0];
    const int*   ei  = (const int*)d_in[1];
    const float* W1  = (const float*)d_in[2];
    const float* b1  = (const float*)d_in[3];
    const float* W2  = (const float*)d_in[4];
    const float* b2  = (const float*)d_in[5];
    const float* W3  = (const float*)d_in[6];
    const float* b3  = (const float*)d_in[7];
    const float* Wc1 = (const float*)d_in[8];
    const float* bc1 = (const float*)d_in[9];
    const float* Wc2 = (const float*)d_in[10];
    const float* bc2 = (const float*)d_in[11];
    float* out = (float*)d_out;

    int n = in_sizes[0] / 64;
    int e = in_sizes[1] / 2;
    const int* src = ei;
    const int* dst = ei + e;
    int nb = (n + SCAN_CHUNK - 1) / SCAN_CHUNK;

    __nv_bfloat16* A;  cudaGetSymbolAddress((void**)&A, g_hA);
    __nv_bfloat16* B;  cudaGetSymbolAddress((void**)&B, g_hB);

    // graph prep
    zero_kernel<<<512, 256>>>(n);
    degree_kernel<<<1024, 256>>>(dst, e);
    scanA_kernel<<<nb, 256>>>(n);                 // deg sums + dis
    cvt_kernel<<<1024, 256>>>(x, A, n * 8);       // x -> dis-prescaled bf16 (T0)
    scanC_kernel<<<nb, 256>>>(nb, n);             // offsets
    fill_kernel<<<1024, 256>>>(src, dst, e);      // CSR (in-place cursors)

    int gg = (n + 127) / 128;
    int ga2 = (n + 15) / 16;  // 2 nodes/warp, 8 warps/block
    dim3 gsplit(ga2, 2);      // feature-split grid for layer-2 agg
    // layer 1: agg(T0) -> unscaled a ; gemm1: relu(a@W1+b1)*dis -> T1 (prescaled)
    agg64_kernel<<<ga2, 256>>>(A, B, n);
    gemm_tc_kernel<64, 128, true, true><<<gg, 256>>>(B, W1, b1, A, n);
    // layer 2: gemm2(T1@W2) = messages ; agg2 (feature-split): relu(dd*sum+b2)*dd
    gemm_tc_kernel<128, 128, false, false><<<gg, 256>>>(A, W2, nullptr, B, n);
    agg128_split_kernel<<<gsplit, 256>>>(B, b2, A, n);
    // layer 3: gemm3(T2@W3) = messages ; agg+pool
    gemm_tc_kernel<128, 64, false, false><<<gg, 256>>>(A, W3, nullptr, B, n);
    agg_pool_kernel<<<ga2, 256>>>(B, b3, n);

    cls_kernel<<<1, 64>>>(Wc1, bc1, Wc2, bc2, out, 1.0f / (float)n);
}

// round 15
// speedup vs baseline: 1.0512x; 1.0450x over previous
#include <cuda_runtime.h>
#include <cuda_bf16.h>
#include <math.h>

#define MAXN 100000
#define MAXE 1600000
#define SCAN_CHUNK 1024

// ---------------- scratch ---------------------------------------------------
__device__ __align__(16) int   g_edeg[MAXN];
__device__ __align__(16) float g_dis[MAXN];
__device__ __align__(16) int   g_off[MAXN + 1];   // after fill: inclusive ends
__device__ __align__(16) int   g_col[MAXE];
__device__ __align__(16) int   g_bsum[128];
__device__ __align__(16) __nv_bfloat16 g_hA[(size_t)MAXN * 128];
__device__ __align__(16) __nv_bfloat16 g_hB[(size_t)MAXN * 128];
__device__ __align__(16) float g_pooled[64];

__device__ __forceinline__ __nv_bfloat162 u2bf2(unsigned u) {
    return *reinterpret_cast<__nv_bfloat162*>(&u);
}

// ---------------- degree histogram over dst (int4 vectorized) ---------------
__global__ void degree_kernel(const int* __restrict__ dst, int e) {
    int i = blockIdx.x * blockDim.x + threadIdx.x;
    int stride = gridDim.x * blockDim.x;
    int e4 = e >> 2;
    for (int k = i; k < e4; k += stride) {
        int4 d = reinterpret_cast<const int4*>(dst)[k];
        atomicAdd(&g_edeg[d.x], 1);
        atomicAdd(&g_edeg[d.y], 1);
        atomicAdd(&g_edeg[d.z], 1);
        atomicAdd(&g_edeg[d.w], 1);
    }
    if (i < (e & 3)) atomicAdd(&g_edeg[dst[e4 * 4 + i]], 1);
}

// ---------------- scan phase A: per-block sums + dis ------------------------
__global__ void scanA_kernel(int n) {
    __shared__ int ssum[8];
    int base = blockIdx.x * SCAN_CHUNK + threadIdx.x * 4;
    int s = 0;
#pragma unroll
    for (int j = 0; j < 4; j++) {
        int idx = base + j;
        if (idx < n) {
            int d = g_edeg[idx];
            s += d;
            g_dis[idx] = rsqrtf((float)(d + 1));
        }
    }
#pragma unroll
    for (int o = 16; o > 0; o >>= 1) s += __shfl_down_sync(0xffffffffu, s, o);
    if ((threadIdx.x & 31) == 0) ssum[threadIdx.x >> 5] = s;
    __syncthreads();
    if (threadIdx.x == 0) {
        int t = 0;
#pragma unroll
        for (int w = 0; w < 8; w++) t += ssum[w];
        g_bsum[blockIdx.x] = t;
    }
}

// ---------------- x -> bf16, prescaled by dis[row] (vectorized x8) ----------
__global__ void cvt_kernel(const float* __restrict__ x, __nv_bfloat16* __restrict__ o,
                           int total8) {
    int i = blockIdx.x * blockDim.x + threadIdx.x;
    int stride = gridDim.x * blockDim.x;
    for (int k = i; k < total8; k += stride) {
        int base = k * 8;
        float dd = g_dis[base >> 6];
        float4 a = *reinterpret_cast<const float4*>(x + base);
        float4 b = *reinterpret_cast<const float4*>(x + base + 4);
        __nv_bfloat162 p0 = __floats2bfloat162_rn(a.x * dd, a.y * dd);
        __nv_bfloat162 p1 = __floats2bfloat162_rn(a.z * dd, a.w * dd);
        __nv_bfloat162 p2 = __floats2bfloat162_rn(b.x * dd, b.y * dd);
        __nv_bfloat162 p3 = __floats2bfloat162_rn(b.z * dd, b.w * dd);
        uint4 r;
        r.x = *reinterpret_cast<unsigned*>(&p0);
        r.y = *reinterpret_cast<unsigned*>(&p1);
        r.z = *reinterpret_cast<unsigned*>(&p2);
        r.w = *reinterpret_cast<unsigned*>(&p3);
        *reinterpret_cast<uint4*>(o + base) = r;
    }
}

// ---------------- scan phase C (with inline block-sum scan) -----------------
__global__ void scanC_kernel(int nb, int n) {
    __shared__ int sb[128];
    __shared__ int sh[256];
    int t = threadIdx.x;
    if (t < 128) sb[t] = (t < nb) ? g_bsum[t] : 0;
    __syncthreads();
#pragma unroll
    for (int o = 1; o < 128; o <<= 1) {
        int u = (t >= o && t < 128) ? sb[t - o] : 0;
        __syncthreads();
        if (t < 128) sb[t] += u;
        __syncthreads();
    }
    int boff = (blockIdx.x == 0) ? 0 : sb[blockIdx.x - 1];
    if (blockIdx.x == 0 && t == 0) g_off[n] = sb[127];

    int base = blockIdx.x * SCAN_CHUNK + t * 4;
    int d[4];
    int s = 0;
#pragma unroll
    for (int j = 0; j < 4; j++) {
        int idx = base + j;
        d[j] = (idx < n) ? g_edeg[idx] : 0;
        s += d[j];
    }
    sh[t] = s;
    __syncthreads();
#pragma unroll
    for (int o = 1; o < 256; o <<= 1) {
        int u = (t >= o) ? sh[t - o] : 0;
        __syncthreads();
        sh[t] += u;
        __syncthreads();
    }
    int run = boff + sh[t] - s;
#pragma unroll
    for (int j = 0; j < 4; j++) {
        int idx = base + j;
        if (idx < n) g_off[idx] = run;
        run += d[j];
    }
}

// ---------------- CSR fill (in-place cursor on g_off, int4 vectorized) ------
__global__ void fill_kernel(const int* __restrict__ src,
                            const int* __restrict__ dst, int e) {
    int i = blockIdx.x * blockDim.x + threadIdx.x;
    int stride = gridDim.x * blockDim.x;
    int e4 = e >> 2;
    for (int k = i; k < e4; k += stride) {
        int4 d = reinterpret_cast<const int4*>(dst)[k];
        int4 s = reinterpret_cast<const int4*>(src)[k];
        g_col[atomicAdd(&g_off[d.x], 1)] = s.x;
        g_col[atomicAdd(&g_off[d.y], 1)] = s.y;
        g_col[atomicAdd(&g_off[d.z], 1)] = s.z;
        g_col[atomicAdd(&g_off[d.w], 1)] = s.w;
    }
    if (i < (e & 3)) {
        int k = e4 * 4 + i;
        g_col[atomicAdd(&g_off[dst[k]], 1)] = src[k];
    }
}

// ---------------- tensor-core GEMM ------------------------------------------
__device__ __forceinline__ unsigned smem_u32(const void* p) {
    return (unsigned)__cvta_generic_to_shared(p);
}
__device__ __forceinline__ void ldsm_x4(unsigned& r0, unsigned& r1, unsigned& r2,
                                        unsigned& r3, unsigned addr) {
    asm volatile("ldmatrix.sync.aligned.m8n8.x4.shared.b16 {%0,%1,%2,%3}, [%4];\n"
                 : "=r"(r0), "=r"(r1), "=r"(r2), "=r"(r3) : "r"(addr));
}
__device__ __forceinline__ void ldsm_x4_t(unsigned& r0, unsigned& r1, unsigned& r2,
                                          unsigned& r3, unsigned addr) {
    asm volatile("ldmatrix.sync.aligned.m8n8.x4.trans.shared.b16 {%0,%1,%2,%3}, [%4];\n"
                 : "=r"(r0), "=r"(r1), "=r"(r2), "=r"(r3) : "r"(addr));
}
__device__ __forceinline__ void mma_bf16(float* d, const unsigned* a, const unsigned* b) {
    asm volatile(
        "mma.sync.aligned.m16n8k16.row.col.f32.bf16.bf16.f32 "
        "{%0,%1,%2,%3}, {%4,%5,%6,%7}, {%8,%9}, {%0,%1,%2,%3};\n"
        : "+f"(d[0]), "+f"(d[1]), "+f"(d[2]), "+f"(d[3])
        : "r"(a[0]), "r"(a[1]), "r"(a[2]), "r"(a[3]), "r"(b[0]), "r"(b[1]));
}

// C[n,HOUT](bf16) = A[n,K](bf16) @ W(f32->bf16); fp32 accum.
template <int K, int HOUT, bool BIASRELU, bool DISSCALE>
__global__ void __launch_bounds__(256, 2)
gemm_tc_kernel(const __nv_bfloat16* __restrict__ A,
               const float* __restrict__ W,
               const float* __restrict__ bias,
               __nv_bfloat16* __restrict__ C, int n) {
    constexpr int KC = 64;
    constexpr int SA_S = KC + 8;
    constexpr int SW_S = HOUT + 8;
    constexpr int NT = HOUT / 8;
    __shared__ __nv_bfloat16 sA[128 * SA_S];
    __shared__ __nv_bfloat16 sW[KC * SW_S];

    int tid = threadIdx.x;
    int wid = tid >> 5;
    int lane = tid & 31;
    int rowBase = blockIdx.x * 128;
    int m0 = wid * 16;

    float acc[NT][4];
#pragma unroll
    for (int t = 0; t < NT; t++)
#pragma unroll
        for (int j = 0; j < 4; j++) acc[t][j] = 0.0f;

    for (int kc = 0; kc < K; kc += KC) {
        constexpr int SEGS = KC / 8;
        for (int i = tid; i < 128 * SEGS; i += 256) {
            int r = i / SEGS, sg = i % SEGS;
            int row = rowBase + r;
            uint4 v = make_uint4(0, 0, 0, 0);
            if (row < n)
                v = *reinterpret_cast<const uint4*>(A + (size_t)row * K + kc + sg * 8);
            *reinterpret_cast<uint4*>(&sA[r * SA_S + sg * 8]) = v;
        }
        constexpr int WC4 = HOUT / 4;
        for (int i = tid; i < KC * WC4; i += 256) {
            int k = i / WC4, c4 = i % WC4;
            float4 w = *reinterpret_cast<const float4*>(W + (size_t)(kc + k) * HOUT + c4 * 4);
            __nv_bfloat162 p0 = __floats2bfloat162_rn(w.x, w.y);
            __nv_bfloat162 p1 = __floats2bfloat162_rn(w.z, w.w);
            uint2 pk;
            pk.x = *reinterpret_cast<unsigned*>(&p0);
            pk.y = *reinterpret_cast<unsigned*>(&p1);
            *reinterpret_cast<uint2*>(&sW[k * SW_S + c4 * 4]) = pk;
        }
        __syncthreads();

#pragma unroll
        for (int ks = 0; ks < KC / 16; ks++) {
            int k0 = ks * 16;
            unsigned a[4];
            {
                int r = m0 + (lane & 15);
                int c = k0 + (lane >> 4) * 8;
                ldsm_x4(a[0], a[1], a[2], a[3], smem_u32(&sA[r * SA_S + c]));
            }
#pragma unroll
            for (int nt2 = 0; nt2 < NT / 2; nt2++) {
                int n0 = nt2 * 16;
                unsigned b[4];
                int rk = k0 + (lane & 15);
                int cn = n0 + (lane >> 4) * 8;
                ldsm_x4_t(b[0], b[1], b[2], b[3], smem_u32(&sW[rk * SW_S + cn]));
                mma_bf16(acc[2 * nt2], a, b);
                mma_bf16(acc[2 * nt2 + 1], a, b + 2);
            }
        }
        __syncthreads();
    }

    int r = lane >> 2;
    int c2 = (lane & 3) * 2;
    int row0 = rowBase + m0 + r;
    int row1 = row0 + 8;
    float ds0 = 1.f, ds1 = 1.f;
    if (DISSCALE) {
        if (row0 < n) ds0 = g_dis[row0];
        if (row1 < n) ds1 = g_dis[row1];
    }
#pragma unroll
    for (int t = 0; t < NT; t++) {
        int col = t * 8 + c2;
        float v0 = acc[t][0], v1 = acc[t][1], v2 = acc[t][2], v3 = acc[t][3];
        if (BIASRELU) {
            float b0 = bias[col], b1 = bias[col + 1];
            v0 = fmaxf(v0 + b0, 0.f); v1 = fmaxf(v1 + b1, 0.f);
            v2 = fmaxf(v2 + b0, 0.f); v3 = fmaxf(v3 + b1, 0.f);
        }
        if (DISSCALE) { v0 *= ds0; v1 *= ds0; v2 *= ds1; v3 *= ds1; }
        if (row0 < n) {
            __nv_bfloat162 p = __floats2bfloat162_rn(v0, v1);
            *reinterpret_cast<unsigned*>(C + (size_t)row0 * HOUT + col) =
                *reinterpret_cast<unsigned*>(&p);
        }
        if (row1 < n) {
            __nv_bfloat162 p = __floats2bfloat162_rn(v2, v3);
            *reinterpret_cast<unsigned*>(C + (size_t)row1 * HOUT + col) =
                *reinterpret_cast<unsigned*>(&p);
        }
    }
}

// ---------------- agg, 2 nodes per warp (16 lanes each), width 64 -----------
__global__ void agg64_kernel(const __nv_bfloat16* __restrict__ h,
                             __nv_bfloat16* __restrict__ out, int n) {
    int warp = (blockIdx.x * blockDim.x + threadIdx.x) >> 5;
    int lane = threadIdx.x & 31;
    int half = lane >> 4;
    int hl   = lane & 15;
    int w = warp * 2 + half;
    bool valid = w < n;

    int beg = 0, end = 0;
    float dd = 0.f;
    if (valid) {
        beg = (w == 0) ? 0 : g_off[w - 1];
        end = g_off[w];
        dd  = g_dis[w];
    }

    float4 a0 = make_float4(0.f, 0.f, 0.f, 0.f);
    float4 a1 = make_float4(0.f, 0.f, 0.f, 0.f);
    int i = beg;
    for (; i + 2 <= end; i += 2) {
        int s0 = g_col[i], s1 = g_col[i + 1];
        uint2 u0 = reinterpret_cast<const uint2*>(h + (size_t)s0 * 64)[hl];
        uint2 u1 = reinterpret_cast<const uint2*>(h + (size_t)s1 * 64)[hl];
        float2 p0 = __bfloat1622float2(u2bf2(u0.x));
        float2 p1 = __bfloat1622float2(u2bf2(u0.y));
        float2 q0 = __bfloat1622float2(u2bf2(u1.x));
        float2 q1 = __bfloat1622float2(u2bf2(u1.y));
        a0.x += p0.x; a0.y += p0.y; a0.z += p1.x; a0.w += p1.y;
        a1.x += q0.x; a1.y += q0.y; a1.z += q1.x; a1.w += q1.y;
    }
    if (i < end) {
        int s0 = g_col[i];
        uint2 u0 = reinterpret_cast<const uint2*>(h + (size_t)s0 * 64)[hl];
        float2 p0 = __bfloat1622float2(u2bf2(u0.x));
        float2 p1 = __bfloat1622float2(u2bf2(u0.y));
        a0.x += p0.x; a0.y += p0.y; a0.z += p1.x; a0.w += p1.y;
    }
    if (valid) {
        uint2 us = reinterpret_cast<const uint2*>(h + (size_t)w * 64)[hl];
        float2 p0 = __bfloat1622float2(u2bf2(us.x));
        float2 p1 = __bfloat1622float2(u2bf2(us.y));
        a0.x += p0.x; a0.y += p0.y; a0.z += p1.x; a0.w += p1.y;

        float ox = dd * (a0.x + a1.x), oy = dd * (a0.y + a1.y);
        float oz = dd * (a0.z + a1.z), ow = dd * (a0.w + a1.w);
        __nv_bfloat162 r0 = __floats2bfloat162_rn(ox, oy);
        __nv_bfloat162 r1 = __floats2bfloat162_rn(oz, ow);
        uint2 r;
        r.x = *reinterpret_cast<unsigned*>(&r0);
        r.y = *reinterpret_cast<unsigned*>(&r1);
        reinterpret_cast<uint2*>(out + (size_t)w * 64)[hl] = r;
    }
}

// ---------------- agg, 2 nodes per warp, width 128, unroll 4 ----------------
__global__ void agg128_kernel(const __nv_bfloat16* __restrict__ h,
                              const float* __restrict__ bias,
                              __nv_bfloat16* __restrict__ out, int n) {
    int warp = (blockIdx.x * blockDim.x + threadIdx.x) >> 5;
    int lane = threadIdx.x & 31;
    int half = lane >> 4;
    int hl   = lane & 15;
    int w = warp * 2 + half;
    bool valid = w < n;

    int beg = 0, end = 0;
    float dd = 0.f;
    if (valid) {
        beg = (w == 0) ? 0 : g_off[w - 1];
        end = g_off[w];
        dd  = g_dis[w];
    }

    float4 aL0 = make_float4(0.f, 0.f, 0.f, 0.f), aH0 = aL0;
    float4 aL1 = aL0, aH1 = aL0;
#define ACCU4(AL, AH, U) { \
        float2 t0 = __bfloat1622float2(u2bf2((U).x)); \
        float2 t1 = __bfloat1622float2(u2bf2((U).y)); \
        float2 t2 = __bfloat1622float2(u2bf2((U).z)); \
        float2 t3 = __bfloat1622float2(u2bf2((U).w)); \
        AL.x += t0.x; AL.y += t0.y; AL.z += t1.x; AL.w += t1.y; \
        AH.x += t2.x; AH.y += t2.y; AH.z += t3.x; AH.w += t3.y; }
    int i = beg;
    for (; i + 4 <= end; i += 4) {
        int s0 = g_col[i], s1 = g_col[i + 1], s2 = g_col[i + 2], s3 = g_col[i + 3];
        uint4 u0 = reinterpret_cast<const uint4*>(h + (size_t)s0 * 128)[hl];
        uint4 u1 = reinterpret_cast<const uint4*>(h + (size_t)s1 * 128)[hl];
        uint4 u2 = reinterpret_cast<const uint4*>(h + (size_t)s2 * 128)[hl];
        uint4 u3 = reinterpret_cast<const uint4*>(h + (size_t)s3 * 128)[hl];
        ACCU4(aL0, aH0, u0)
        ACCU4(aL1, aH1, u1)
        ACCU4(aL0, aH0, u2)
        ACCU4(aL1, aH1, u3)
    }
    for (; i < end; i++) {
        uint4 u0 = reinterpret_cast<const uint4*>(h + (size_t)g_col[i] * 128)[hl];
        ACCU4(aL0, aH0, u0)
    }
    if (valid) {
        uint4 us = reinterpret_cast<const uint4*>(h + (size_t)w * 128)[hl];
        ACCU4(aL0, aH0, us)

        float4 bb0 = reinterpret_cast<const float4*>(bias)[hl * 2];
        float4 bb1 = reinterpret_cast<const float4*>(bias)[hl * 2 + 1];
        float o0 = fmaxf(dd * (aL0.x + aL1.x) + bb0.x, 0.f) * dd;
        float o1 = fmaxf(dd * (aL0.y + aL1.y) + bb0.y, 0.f) * dd;
        float o2 = fmaxf(dd * (aL0.z + aL1.z) + bb0.z, 0.f) * dd;
        float o3 = fmaxf(dd * (aL0.w + aL1.w) + bb0.w, 0.f) * dd;
        float o4 = fmaxf(dd * (aH0.x + aH1.x) + bb1.x, 0.f) * dd;
        float o5 = fmaxf(dd * (aH0.y + aH1.y) + bb1.y, 0.f) * dd;
        float o6 = fmaxf(dd * (aH0.z + aH1.z) + bb1.z, 0.f) * dd;
        float o7 = fmaxf(dd * (aH0.w + aH1.w) + bb1.w, 0.f) * dd;
        __nv_bfloat162 r0 = __floats2bfloat162_rn(o0, o1);
        __nv_bfloat162 r1 = __floats2bfloat162_rn(o2, o3);
        __nv_bfloat162 r2 = __floats2bfloat162_rn(o4, o5);
        __nv_bfloat162 r3 = __floats2bfloat162_rn(o6, o7);
        uint4 r;
        r.x = *reinterpret_cast<unsigned*>(&r0);
        r.y = *reinterpret_cast<unsigned*>(&r1);
        r.z = *reinterpret_cast<unsigned*>(&r2);
        r.w = *reinterpret_cast<unsigned*>(&r3);
        reinterpret_cast<uint4*>(out + (size_t)w * 128)[hl] = r;
    }
#undef ACCU4
}

// ---------------- layer-3 agg (2 nodes/warp, width 64) + mean pool ----------
__global__ void agg_pool_kernel(const __nv_bfloat16* __restrict__ h,
                                const float* __restrict__ bias, int n) {
    __shared__ float sp[64];
    int tid = threadIdx.x;
    if (tid < 64) sp[tid] = 0.f;
    __syncthreads();

    int warp = (blockIdx.x * blockDim.x + tid) >> 5;
    int lane = tid & 31;
    int half = lane >> 4;
    int hl   = lane & 15;
    int w = warp * 2 + half;
    bool valid = w < n;

    int beg = 0, end = 0;
    float dd = 0.f;
    if (valid) {
        beg = (w == 0) ? 0 : g_off[w - 1];
        end = g_off[w];
        dd  = g_dis[w];
    }

    float4 a0 = make_float4(0.f, 0.f, 0.f, 0.f);
    float4 a1 = make_float4(0.f, 0.f, 0.f, 0.f);
    int i = beg;
    for (; i + 2 <= end; i += 2) {
        int s0 = g_col[i], s1 = g_col[i + 1];
        uint2 u0 = reinterpret_cast<const uint2*>(h + (size_t)s0 * 64)[hl];
        uint2 u1 = reinterpret_cast<const uint2*>(h + (size_t)s1 * 64)[hl];
        float2 p0 = __bfloat1622float2(u2bf2(u0.x));
        float2 p1 = __bfloat1622float2(u2bf2(u0.y));
        float2 q0 = __bfloat1622float2(u2bf2(u1.x));
        float2 q1 = __bfloat1622float2(u2bf2(u1.y));
        a0.x += p0.x; a0.y += p0.y; a0.z += p1.x; a0.w += p1.y;
        a1.x += q0.x; a1.y += q0.y; a1.z += q1.x; a1.w += q1.y;
    }
    if (i < end) {
        int s0 = g_col[i];
        uint2 u0 = reinterpret_cast<const uint2*>(h + (size_t)s0 * 64)[hl];
        float2 p0 = __bfloat1622float2(u2bf2(u0.x));
        float2 p1 = __bfloat1622float2(u2bf2(u0.y));
        a0.x += p0.x; a0.y += p0.y; a0.z += p1.x; a0.w += p1.y;
    }
    if (valid) {
        uint2 us = reinterpret_cast<const uint2*>(h + (size_t)w * 64)[hl];
        float2 p0 = __bfloat1622float2(u2bf2(us.x));
        float2 p1 = __bfloat1622float2(u2bf2(us.y));
        a0.x += p0.x; a0.y += p0.y; a0.z += p1.x; a0.w += p1.y;

        float4 bb = reinterpret_cast<const float4*>(bias)[hl];
        float o0 = fmaxf(dd * (a0.x + a1.x) + bb.x, 0.f);
        float o1 = fmaxf(dd * (a0.y + a1.y) + bb.y, 0.f);
        float o2 = fmaxf(dd * (a0.z + a1.z) + bb.z, 0.f);
        float o3 = fmaxf(dd * (a0.w + a1.w) + bb.w, 0.f);
        atomicAdd(&sp[hl * 4 + 0], o0);
        atomicAdd(&sp[hl * 4 + 1], o1);
        atomicAdd(&sp[hl * 4 + 2], o2);
        atomicAdd(&sp[hl * 4 + 3], o3);
    }
    __syncthreads();
    if (tid < 64) atomicAdd(&g_pooled[tid], sp[tid]);
}

// ---------------- classifier + softmax --------------------------------------
__global__ void cls_kernel(const float* __restrict__ Wc1, const float* __restrict__ bc1,
                           const float* __restrict__ Wc2, const float* __restrict__ bc2,
                           float* __restrict__ out, float invN) {
    __shared__ float z[32];
    int t = threadIdx.x;
    if (t < 32) {
        float a = bc1[t];
        for (int i = 0; i < 64; i++)
            a = fmaf(g_pooled[i] * invN, Wc1[i * 32 + t], a);
        z[t] = fmaxf(a, 0.f);
    }
    __syncthreads();
    if (t == 0) {
        float l0 = bc2[0], l1 = bc2[1];
        for (int j = 0; j < 32; j++) {
            l0 = fmaf(z[j], Wc2[j * 2 + 0], l0);
            l1 = fmaf(z[j], Wc2[j * 2 + 1], l1);
        }
        float m = fmaxf(l0, l1);
        float e0 = expf(l0 - m), e1 = expf(l1 - m);
        float s = e0 + e1;
        out[0] = e0 / s;
        out[1] = e1 / s;
    }
}

// ---------------- launch -----------------------------------------------------
extern "C" void kernel_launch(void* const* d_in, const int* in_sizes, int n_in,
                              void* d_out, int out_size) {
    const float* x   = (const float*)d_in[0];
    const int*   ei  = (const int*)d_in[1];
    const float* W1  = (const float*)d_in[2];
    const float* b1  = (const float*)d_in[3];
    const float* W2  = (const float*)d_in[4];
    const float* b2  = (const float*)d_in[5];
    const float* W3  = (const float*)d_in[6];
    const float* b3  = (const float*)d_in[7];
    const float* Wc1 = (const float*)d_in[8];
    const float* bc1 = (const float*)d_in[9];
    const float* Wc2 = (const float*)d_in[10];
    const float* bc2 = (const float*)d_in[11];
    float* out = (float*)d_out;

    int n = in_sizes[0] / 64;
    int e = in_sizes[1] / 2;
    const int* src = ei;
    const int* dst = ei + e;
    int nb = (n + SCAN_CHUNK - 1) / SCAN_CHUNK;

    __nv_bfloat16* A;  cudaGetSymbolAddress((void**)&A, g_hA);
    __nv_bfloat16* B;  cudaGetSymbolAddress((void**)&B, g_hB);
    int*   edeg;   cudaGetSymbolAddress((void**)&edeg, g_edeg);
    float* pooled; cudaGetSymbolAddress((void**)&pooled, g_pooled);

    // host-side resources, created once on the (uncaptured) correctness call
    static cudaStream_t side = nullptr;
    static cudaEvent_t evA = nullptr, evC = nullptr;
    if (side == nullptr) {
        cudaStreamCreateWithFlags(&side, cudaStreamNonBlocking);
        cudaEventCreateWithFlags(&evA, cudaEventDisableTiming);
        cudaEventCreateWithFlags(&evC, cudaEventDisableTiming);
    }

    // graph prep (default stream)
    cudaMemsetAsync(edeg, 0, (size_t)n * sizeof(int), 0);
    cudaMemsetAsync(pooled, 0, 64 * sizeof(float), 0);
    degree_kernel<<<1024, 256>>>(dst, e);
    scanA_kernel<<<nb, 256>>>(n);                 // deg sums + dis

    // fork: cvt (needs only dis) overlaps scanC + fill on the side stream
    cudaEventRecord(evA, 0);
    cudaStreamWaitEvent(side, evA, 0);
    cvt_kernel<<<1024, 256, 0, side>>>(x, A, n * 8);   // x -> dis-prescaled bf16 (T0)
    cudaEventRecord(evC, side);

    scanC_kernel<<<nb, 256>>>(nb, n);             // offsets
    fill_kernel<<<1024, 256>>>(src, dst, e);      // CSR (in-place cursors)
    cudaStreamWaitEvent(0, evC, 0);               // join before agg64

    int gg = (n + 127) / 128;
    int ga2 = (n + 15) / 16;  // 2 nodes/warp, 8 warps/block
    // layer 1: agg(T0) -> unscaled a ; gemm1: relu(a@W1+b1)*dis -> T1 (prescaled)
    agg64_kernel<<<ga2, 256>>>(A, B, n);
    gemm_tc_kernel<64, 128, true, true><<<gg, 256>>>(B, W1, b1, A, n);
    // layer 2: gemm2(T1@W2) = messages ; agg2: relu(dd*sum+b2)*dd -> T2 (prescaled)
    gemm_tc_kernel<128, 128, false, false><<<gg, 256>>>(A, W2, nullptr, B, n);
    agg128_kernel<<<ga2, 256>>>(B, b2, A, n);
    // layer 3: gemm3(T2@W3) = messages ; agg+pool
    gemm_tc_kernel<128, 64, false, false><<<gg, 256>>>(A, W3, nullptr, B, n);
    agg_pool_kernel<<<ga2, 256>>>(B, b3, n);

    cls_kernel<<<1, 64>>>(Wc1, bc1, Wc2, bc2, out, 1.0f / (float)n);
}

// round 16
// speedup vs baseline: 1.0596x; 1.0080x over previous
#include <cuda_runtime.h>
#include <cuda_bf16.h>
#include <math.h>

#define MAXN 100000
#define MAXE 1600000
#define SCAN_CHUNK 1024

// ---------------- scratch ---------------------------------------------------
__device__ __align__(16) int   g_edeg[MAXN];
__device__ __align__(16) float g_dis[MAXN];
__device__ __align__(16) int   g_off[MAXN + 1];   // after fill: inclusive ends
__device__ __align__(16) int   g_col[MAXE];
__device__ __align__(16) int   g_bsum[128];
__device__ __align__(16) __nv_bfloat16 g_hA[(size_t)MAXN * 128];
__device__ __align__(16) __nv_bfloat16 g_hB[(size_t)MAXN * 128];
__device__ __align__(16) float g_pooled[64];

__device__ __forceinline__ __nv_bfloat162 u2bf2(unsigned u) {
    return *reinterpret_cast<__nv_bfloat162*>(&u);
}

// ---------------- degree histogram over dst (int4 vectorized) ---------------
__global__ void degree_kernel(const int* __restrict__ dst, int e) {
    int i = blockIdx.x * blockDim.x + threadIdx.x;
    int stride = gridDim.x * blockDim.x;
    int e4 = e >> 2;
    for (int k = i; k < e4; k += stride) {
        int4 d = reinterpret_cast<const int4*>(dst)[k];
        atomicAdd(&g_edeg[d.x], 1);
        atomicAdd(&g_edeg[d.y], 1);
        atomicAdd(&g_edeg[d.z], 1);
        atomicAdd(&g_edeg[d.w], 1);
    }
    if (i < (e & 3)) atomicAdd(&g_edeg[dst[e4 * 4 + i]], 1);
}

// ---------------- scan phase A: per-block sums + dis ------------------------
__global__ void scanA_kernel(int n) {
    __shared__ int ssum[8];
    int base = blockIdx.x * SCAN_CHUNK + threadIdx.x * 4;
    int s = 0;
#pragma unroll
    for (int j = 0; j < 4; j++) {
        int idx = base + j;
        if (idx < n) {
            int d = g_edeg[idx];
            s += d;
            g_dis[idx] = rsqrtf((float)(d + 1));
        }
    }
#pragma unroll
    for (int o = 16; o > 0; o >>= 1) s += __shfl_down_sync(0xffffffffu, s, o);
    if ((threadIdx.x & 31) == 0) ssum[threadIdx.x >> 5] = s;
    __syncthreads();
    if (threadIdx.x == 0) {
        int t = 0;
#pragma unroll
        for (int w = 0; w < 8; w++) t += ssum[w];
        g_bsum[blockIdx.x] = t;
    }
}

// ---------------- x -> bf16, prescaled by dis[row] (vectorized x8) ----------
__global__ void cvt_kernel(const float* __restrict__ x, __nv_bfloat16* __restrict__ o,
                           int total8) {
    int i = blockIdx.x * blockDim.x + threadIdx.x;
    int stride = gridDim.x * blockDim.x;
    for (int k = i; k < total8; k += stride) {
        int base = k * 8;
        float dd = g_dis[base >> 6];
        float4 a = *reinterpret_cast<const float4*>(x + base);
        float4 b = *reinterpret_cast<const float4*>(x + base + 4);
        __nv_bfloat162 p0 = __floats2bfloat162_rn(a.x * dd, a.y * dd);
        __nv_bfloat162 p1 = __floats2bfloat162_rn(a.z * dd, a.w * dd);
        __nv_bfloat162 p2 = __floats2bfloat162_rn(b.x * dd, b.y * dd);
        __nv_bfloat162 p3 = __floats2bfloat162_rn(b.z * dd, b.w * dd);
        uint4 r;
        r.x = *reinterpret_cast<unsigned*>(&p0);
        r.y = *reinterpret_cast<unsigned*>(&p1);
        r.z = *reinterpret_cast<unsigned*>(&p2);
        r.w = *reinterpret_cast<unsigned*>(&p3);
        *reinterpret_cast<uint4*>(o + base) = r;
    }
}

// ---------------- scan phase C (with inline block-sum scan) -----------------
__global__ void scanC_kernel(int nb, int n) {
    __shared__ int sb[128];
    __shared__ int sh[256];
    int t = threadIdx.x;
    if (t < 128) sb[t] = (t < nb) ? g_bsum[t] : 0;
    __syncthreads();
#pragma unroll
    for (int o = 1; o < 128; o <<= 1) {
        int u = (t >= o && t < 128) ? sb[t - o] : 0;
        __syncthreads();
        if (t < 128) sb[t] += u;
        __syncthreads();
    }
    int boff = (blockIdx.x == 0) ? 0 : sb[blockIdx.x - 1];
    if (blockIdx.x == 0 && t == 0) g_off[n] = sb[127];

    int base = blockIdx.x * SCAN_CHUNK + t * 4;
    int d[4];
    int s = 0;
#pragma unroll
    for (int j = 0; j < 4; j++) {
        int idx = base + j;
        d[j] = (idx < n) ? g_edeg[idx] : 0;
        s += d[j];
    }
    sh[t] = s;
    __syncthreads();
#pragma unroll
    for (int o = 1; o < 256; o <<= 1) {
        int u = (t >= o) ? sh[t - o] : 0;
        __syncthreads();
        sh[t] += u;
        __syncthreads();
    }
    int run = boff + sh[t] - s;
#pragma unroll
    for (int j = 0; j < 4; j++) {
        int idx = base + j;
        if (idx < n) g_off[idx] = run;
        run += d[j];
    }
}

// ---------------- CSR fill (in-place cursor on g_off, int4 vectorized) ------
__global__ void fill_kernel(const int* __restrict__ src,
                            const int* __restrict__ dst, int e) {
    int i = blockIdx.x * blockDim.x + threadIdx.x;
    int stride = gridDim.x * blockDim.x;
    int e4 = e >> 2;
    for (int k = i; k < e4; k += stride) {
        int4 d = reinterpret_cast<const int4*>(dst)[k];
        int4 s = reinterpret_cast<const int4*>(src)[k];
        g_col[atomicAdd(&g_off[d.x], 1)] = s.x;
        g_col[atomicAdd(&g_off[d.y], 1)] = s.y;
        g_col[atomicAdd(&g_off[d.z], 1)] = s.z;
        g_col[atomicAdd(&g_off[d.w], 1)] = s.w;
    }
    if (i < (e & 3)) {
        int k = e4 * 4 + i;
        g_col[atomicAdd(&g_off[dst[k]], 1)] = src[k];
    }
}

// ---------------- helpers ----------------------------------------------------
__device__ __forceinline__ unsigned smem_u32(const void* p) {
    return (unsigned)__cvta_generic_to_shared(p);
}
__device__ __forceinline__ void ldsm_x4(unsigned& r0, unsigned& r1, unsigned& r2,
                                        unsigned& r3, unsigned addr) {
    asm volatile("ldmatrix.sync.aligned.m8n8.x4.shared.b16 {%0,%1,%2,%3}, [%4];\n"
                 : "=r"(r0), "=r"(r1), "=r"(r2), "=r"(r3) : "r"(addr));
}
__device__ __forceinline__ void ldsm_x4_t(unsigned& r0, unsigned& r1, unsigned& r2,
                                          unsigned& r3, unsigned addr) {
    asm volatile("ldmatrix.sync.aligned.m8n8.x4.trans.shared.b16 {%0,%1,%2,%3}, [%4];\n"
                 : "=r"(r0), "=r"(r1), "=r"(r2), "=r"(r3) : "r"(addr));
}
__device__ __forceinline__ void mma_bf16(float* d, const unsigned* a, const unsigned* b) {
    asm volatile(
        "mma.sync.aligned.m16n8k16.row.col.f32.bf16.bf16.f32 "
        "{%0,%1,%2,%3}, {%4,%5,%6,%7}, {%8,%9}, {%0,%1,%2,%3};\n"
        : "+f"(d[0]), "+f"(d[1]), "+f"(d[2]), "+f"(d[3])
        : "r"(a[0]), "r"(a[1]), "r"(a[2]), "r"(a[3]), "r"(b[0]), "r"(b[1]));
}

// ---------------- FUSED layer 1: agg(width 64) -> GEMM(64->128)+bias+relu*dis
// 512 threads; block owns 128 nodes. Phase 1: 16 warps aggregate 2 nodes/warp
// x 4 passes directly into sA. Phase 2: mma, 2 warps per 16-row stripe
// (each takes a 64-col N-half). Output bf16 dis-prescaled table.
__global__ void __launch_bounds__(512, 2)
agg_gemm1_kernel(const __nv_bfloat16* __restrict__ h,
                 const float* __restrict__ W,
                 const float* __restrict__ bias,
                 __nv_bfloat16* __restrict__ C, int n) {
    constexpr int KC = 64;         // = K
    constexpr int HOUT = 128;
    constexpr int SA_S = KC + 8;   // 72
    constexpr int SW_S = HOUT + 8; // 136
    __shared__ __nv_bfloat16 sA[128 * SA_S];
    __shared__ __nv_bfloat16 sW[KC * SW_S];

    int tid = threadIdx.x;
    int wid = tid >> 5;            // 0..15
    int lane = tid & 31;
    int rowBase = blockIdx.x * 128;

    // ---- load W (64 x 128) into sW ----
    constexpr int WC4 = HOUT / 4;
    for (int i = tid; i < KC * WC4; i += 512) {
        int k = i / WC4, c4 = i % WC4;
        float4 w = *reinterpret_cast<const float4*>(W + (size_t)k * HOUT + c4 * 4);
        __nv_bfloat162 p0 = __floats2bfloat162_rn(w.x, w.y);
        __nv_bfloat162 p1 = __floats2bfloat162_rn(w.z, w.w);
        uint2 pk;
        pk.x = *reinterpret_cast<unsigned*>(&p0);
        pk.y = *reinterpret_cast<unsigned*>(&p1);
        *reinterpret_cast<uint2*>(&sW[k * SW_S + c4 * 4]) = pk;
    }

    // ---- phase 1: aggregate 128 nodes into sA (2 nodes/warp x 4 passes) ----
    int half = lane >> 4;
    int hl   = lane & 15;
#pragma unroll
    for (int p = 0; p < 4; p++) {
        int r = p * 32 + wid * 2 + half;     // local row 0..127
        int w = rowBase + r;
        uint2 res = make_uint2(0u, 0u);
        if (w < n) {
            int beg = (w == 0) ? 0 : g_off[w - 1];
            int end = g_off[w];
            float dd = g_dis[w];
            float4 a0 = make_float4(0.f, 0.f, 0.f, 0.f);
            float4 a1 = make_float4(0.f, 0.f, 0.f, 0.f);
            int i = beg;
            for (; i + 2 <= end; i += 2) {
                int s0 = g_col[i], s1 = g_col[i + 1];
                uint2 u0 = reinterpret_cast<const uint2*>(h + (size_t)s0 * 64)[hl];
                uint2 u1 = reinterpret_cast<const uint2*>(h + (size_t)s1 * 64)[hl];
                float2 p0 = __bfloat1622float2(u2bf2(u0.x));
                float2 p1 = __bfloat1622float2(u2bf2(u0.y));
                float2 q0 = __bfloat1622float2(u2bf2(u1.x));
                float2 q1 = __bfloat1622float2(u2bf2(u1.y));
                a0.x += p0.x; a0.y += p0.y; a0.z += p1.x; a0.w += p1.y;
                a1.x += q0.x; a1.y += q0.y; a1.z += q1.x; a1.w += q1.y;
            }
            if (i < end) {
                int s0 = g_col[i];
                uint2 u0 = reinterpret_cast<const uint2*>(h + (size_t)s0 * 64)[hl];
                float2 p0 = __bfloat1622float2(u2bf2(u0.x));
                float2 p1 = __bfloat1622float2(u2bf2(u0.y));
                a0.x += p0.x; a0.y += p0.y; a0.z += p1.x; a0.w += p1.y;
            }
            uint2 us = reinterpret_cast<const uint2*>(h + (size_t)w * 64)[hl];
            float2 p0 = __bfloat1622float2(u2bf2(us.x));
            float2 p1 = __bfloat1622float2(u2bf2(us.y));
            a0.x += p0.x; a0.y += p0.y; a0.z += p1.x; a0.w += p1.y;

            __nv_bfloat162 r0 = __floats2bfloat162_rn(dd * (a0.x + a1.x),
                                                      dd * (a0.y + a1.y));
            __nv_bfloat162 r1 = __floats2bfloat162_rn(dd * (a0.z + a1.z),
                                                      dd * (a0.w + a1.w));
            res.x = *reinterpret_cast<unsigned*>(&r0);
            res.y = *reinterpret_cast<unsigned*>(&r1);
        }
        *reinterpret_cast<uint2*>(&sA[r * SA_S + hl * 4]) = res;
    }
    __syncthreads();

    // ---- phase 2: mma; 2 warps per 16-row stripe, each one 64-col N-half ---
    int stripe = wid >> 1;   // 0..7
    int nh = wid & 1;        // 0,1
    int m0 = stripe * 16;
    float acc[8][4];
#pragma unroll
    for (int t = 0; t < 8; t++)
#pragma unroll
        for (int j = 0; j < 4; j++) acc[t][j] = 0.0f;

#pragma unroll
    for (int ks = 0; ks < 4; ks++) {
        int k0 = ks * 16;
        unsigned a[4];
        {
            int r = m0 + (lane & 15);
            int c = k0 + (lane >> 4) * 8;
            ldsm_x4(a[0], a[1], a[2], a[3], smem_u32(&sA[r * SA_S + c]));
        }
#pragma unroll
        for (int nt2 = 0; nt2 < 4; nt2++) {
            int n0 = nh * 64 + nt2 * 16;
            unsigned b[4];
            int rk = k0 + (lane & 15);
            int cn = n0 + (lane >> 4) * 8;
            ldsm_x4_t(b[0], b[1], b[2], b[3], smem_u32(&sW[rk * SW_S + cn]));
            mma_bf16(acc[2 * nt2], a, b);
            mma_bf16(acc[2 * nt2 + 1], a, b + 2);
        }
    }

    // ---- epilogue: bias + relu, * dis, store bf16 ----
    int r = lane >> 2;
    int c2 = (lane & 3) * 2;
    int row0 = rowBase + m0 + r;
    int row1 = row0 + 8;
    float ds0 = (row0 < n) ? g_dis[row0] : 0.f;
    float ds1 = (row1 < n) ? g_dis[row1] : 0.f;
#pragma unroll
    for (int t = 0; t < 8; t++) {
        int col = nh * 64 + t * 8 + c2;
        float b0 = bias[col], b1 = bias[col + 1];
        float v0 = fmaxf(acc[t][0] + b0, 0.f) * ds0;
        float v1 = fmaxf(acc[t][1] + b1, 0.f) * ds0;
        float v2 = fmaxf(acc[t][2] + b0, 0.f) * ds1;
        float v3 = fmaxf(acc[t][3] + b1, 0.f) * ds1;
        if (row0 < n) {
            __nv_bfloat162 p = __floats2bfloat162_rn(v0, v1);
            *reinterpret_cast<unsigned*>(C + (size_t)row0 * 128 + col) =
                *reinterpret_cast<unsigned*>(&p);
        }
        if (row1 < n) {
            __nv_bfloat162 p = __floats2bfloat162_rn(v2, v3);
            *reinterpret_cast<unsigned*>(C + (size_t)row1 * 128 + col) =
                *reinterpret_cast<unsigned*>(&p);
        }
    }
}

// ---------------- tensor-core GEMM (layers 2,3) ------------------------------
template <int K, int HOUT, bool BIASRELU, bool DISSCALE>
__global__ void __launch_bounds__(256, 2)
gemm_tc_kernel(const __nv_bfloat16* __restrict__ A,
               const float* __restrict__ W,
               const float* __restrict__ bias,
               __nv_bfloat16* __restrict__ C, int n) {
    constexpr int KC = 64;
    constexpr int SA_S = KC + 8;
    constexpr int SW_S = HOUT + 8;
    constexpr int NT = HOUT / 8;
    __shared__ __nv_bfloat16 sA[128 * SA_S];
    __shared__ __nv_bfloat16 sW[KC * SW_S];

    int tid = threadIdx.x;
    int wid = tid >> 5;
    int lane = tid & 31;
    int rowBase = blockIdx.x * 128;
    int m0 = wid * 16;

    float acc[NT][4];
#pragma unroll
    for (int t = 0; t < NT; t++)
#pragma unroll
        for (int j = 0; j < 4; j++) acc[t][j] = 0.0f;

    for (int kc = 0; kc < K; kc += KC) {
        constexpr int SEGS = KC / 8;
        for (int i = tid; i < 128 * SEGS; i += 256) {
            int r = i / SEGS, sg = i % SEGS;
            int row = rowBase + r;
            uint4 v = make_uint4(0, 0, 0, 0);
            if (row < n)
                v = *reinterpret_cast<const uint4*>(A + (size_t)row * K + kc + sg * 8);
            *reinterpret_cast<uint4*>(&sA[r * SA_S + sg * 8]) = v;
        }
        constexpr int WC4 = HOUT / 4;
        for (int i = tid; i < KC * WC4; i += 256) {
            int k = i / WC4, c4 = i % WC4;
            float4 w = *reinterpret_cast<const float4*>(W + (size_t)(kc + k) * HOUT + c4 * 4);
            __nv_bfloat162 p0 = __floats2bfloat162_rn(w.x, w.y);
            __nv_bfloat162 p1 = __floats2bfloat162_rn(w.z, w.w);
            uint2 pk;
            pk.x = *reinterpret_cast<unsigned*>(&p0);
            pk.y = *reinterpret_cast<unsigned*>(&p1);
            *reinterpret_cast<uint2*>(&sW[k * SW_S + c4 * 4]) = pk;
        }
        __syncthreads();

#pragma unroll
        for (int ks = 0; ks < KC / 16; ks++) {
            int k0 = ks * 16;
            unsigned a[4];
            {
                int r = m0 + (lane & 15);
                int c = k0 + (lane >> 4) * 8;
                ldsm_x4(a[0], a[1], a[2], a[3], smem_u32(&sA[r * SA_S + c]));
            }
#pragma unroll
            for (int nt2 = 0; nt2 < NT / 2; nt2++) {
                int n0 = nt2 * 16;
                unsigned b[4];
                int rk = k0 + (lane & 15);
                int cn = n0 + (lane >> 4) * 8;
                ldsm_x4_t(b[0], b[1], b[2], b[3], smem_u32(&sW[rk * SW_S + cn]));
                mma_bf16(acc[2 * nt2], a, b);
                mma_bf16(acc[2 * nt2 + 1], a, b + 2);
            }
        }
        __syncthreads();
    }

    int r = lane >> 2;
    int c2 = (lane & 3) * 2;
    int row0 = rowBase + m0 + r;
    int row1 = row0 + 8;
    float ds0 = 1.f, ds1 = 1.f;
    if (DISSCALE) {
        if (row0 < n) ds0 = g_dis[row0];
        if (row1 < n) ds1 = g_dis[row1];
    }
#pragma unroll
    for (int t = 0; t < NT; t++) {
        int col = t * 8 + c2;
        float v0 = acc[t][0], v1 = acc[t][1], v2 = acc[t][2], v3 = acc[t][3];
        if (BIASRELU) {
            float b0 = bias[col], b1 = bias[col + 1];
            v0 = fmaxf(v0 + b0, 0.f); v1 = fmaxf(v1 + b1, 0.f);
            v2 = fmaxf(v2 + b0, 0.f); v3 = fmaxf(v3 + b1, 0.f);
        }
        if (DISSCALE) { v0 *= ds0; v1 *= ds0; v2 *= ds1; v3 *= ds1; }
        if (row0 < n) {
            __nv_bfloat162 p = __floats2bfloat162_rn(v0, v1);
            *reinterpret_cast<unsigned*>(C + (size_t)row0 * HOUT + col) =
                *reinterpret_cast<unsigned*>(&p);
        }
        if (row1 < n) {
            __nv_bfloat162 p = __floats2bfloat162_rn(v2, v3);
            *reinterpret_cast<unsigned*>(C + (size_t)row1 * HOUT + col) =
                *reinterpret_cast<unsigned*>(&p);
        }
    }
}

// ---------------- agg, 2 nodes per warp, width 128, unroll 4 ----------------
__global__ void agg128_kernel(const __nv_bfloat16* __restrict__ h,
                              const float* __restrict__ bias,
                              __nv_bfloat16* __restrict__ out, int n) {
    int warp = (blockIdx.x * blockDim.x + threadIdx.x) >> 5;
    int lane = threadIdx.x & 31;
    int half = lane >> 4;
    int hl   = lane & 15;
    int w = warp * 2 + half;
    bool valid = w < n;

    int beg = 0, end = 0;
    float dd = 0.f;
    if (valid) {
        beg = (w == 0) ? 0 : g_off[w - 1];
        end = g_off[w];
        dd  = g_dis[w];
    }

    float4 aL0 = make_float4(0.f, 0.f, 0.f, 0.f), aH0 = aL0;
    float4 aL1 = aL0, aH1 = aL0;
#define ACCU4(AL, AH, U) { \
        float2 t0 = __bfloat1622float2(u2bf2((U).x)); \
        float2 t1 = __bfloat1622float2(u2bf2((U).y)); \
        float2 t2 = __bfloat1622float2(u2bf2((U).z)); \
        float2 t3 = __bfloat1622float2(u2bf2((U).w)); \
        AL.x += t0.x; AL.y += t0.y; AL.z += t1.x; AL.w += t1.y; \
        AH.x += t2.x; AH.y += t2.y; AH.z += t3.x; AH.w += t3.y; }
    int i = beg;
    for (; i + 4 <= end; i += 4) {
        int s0 = g_col[i], s1 = g_col[i + 1], s2 = g_col[i + 2], s3 = g_col[i + 3];
        uint4 u0 = reinterpret_cast<const uint4*>(h + (size_t)s0 * 128)[hl];
        uint4 u1 = reinterpret_cast<const uint4*>(h + (size_t)s1 * 128)[hl];
        uint4 u2 = reinterpret_cast<const uint4*>(h + (size_t)s2 * 128)[hl];
        uint4 u3 = reinterpret_cast<const uint4*>(h + (size_t)s3 * 128)[hl];
        ACCU4(aL0, aH0, u0)
        ACCU4(aL1, aH1, u1)
        ACCU4(aL0, aH0, u2)
        ACCU4(aL1, aH1, u3)
    }
    for (; i < end; i++) {
        uint4 u0 = reinterpret_cast<const uint4*>(h + (size_t)g_col[i] * 128)[hl];
        ACCU4(aL0, aH0, u0)
    }
    if (valid) {
        uint4 us = reinterpret_cast<const uint4*>(h + (size_t)w * 128)[hl];
        ACCU4(aL0, aH0, us)

        float4 bb0 = reinterpret_cast<const float4*>(bias)[hl * 2];
        float4 bb1 = reinterpret_cast<const float4*>(bias)[hl * 2 + 1];
        float o0 = fmaxf(dd * (aL0.x + aL1.x) + bb0.x, 0.f) * dd;
        float o1 = fmaxf(dd * (aL0.y + aL1.y) + bb0.y, 0.f) * dd;
        float o2 = fmaxf(dd * (aL0.z + aL1.z) + bb0.z, 0.f) * dd;
        float o3 = fmaxf(dd * (aL0.w + aL1.w) + bb0.w, 0.f) * dd;
        float o4 = fmaxf(dd * (aH0.x + aH1.x) + bb1.x, 0.f) * dd;
        float o5 = fmaxf(dd * (aH0.y + aH1.y) + bb1.y, 0.f) * dd;
        float o6 = fmaxf(dd * (aH0.z + aH1.z) + bb1.z, 0.f) * dd;
        float o7 = fmaxf(dd * (aH0.w + aH1.w) + bb1.w, 0.f) * dd;
        __nv_bfloat162 r0 = __floats2bfloat162_rn(o0, o1);
        __nv_bfloat162 r1 = __floats2bfloat162_rn(o2, o3);
        __nv_bfloat162 r2 = __floats2bfloat162_rn(o4, o5);
        __nv_bfloat162 r3 = __floats2bfloat162_rn(o6, o7);
        uint4 r;
        r.x = *reinterpret_cast<unsigned*>(&r0);
        r.y = *reinterpret_cast<unsigned*>(&r1);
        r.z = *reinterpret_cast<unsigned*>(&r2);
        r.w = *reinterpret_cast<unsigned*>(&r3);
        reinterpret_cast<uint4*>(out + (size_t)w * 128)[hl] = r;
    }
#undef ACCU4
}

// ---------------- layer-3 agg (2 nodes/warp, width 64) + mean pool ----------
__global__ void agg_pool_kernel(const __nv_bfloat16* __restrict__ h,
                                const float* __restrict__ bias, int n) {
    __shared__ float sp[64];
    int tid = threadIdx.x;
    if (tid < 64) sp[tid] = 0.f;
    __syncthreads();

    int warp = (blockIdx.x * blockDim.x + tid) >> 5;
    int lane = tid & 31;
    int half = lane >> 4;
    int hl   = lane & 15;
    int w = warp * 2 + half;
    bool valid = w < n;

    int beg = 0, end = 0;
    float dd = 0.f;
    if (valid) {
        beg = (w == 0) ? 0 : g_off[w - 1];
        end = g_off[w];
        dd  = g_dis[w];
    }

    float4 a0 = make_float4(0.f, 0.f, 0.f, 0.f);
    float4 a1 = make_float4(0.f, 0.f, 0.f, 0.f);
    int i = beg;
    for (; i + 2 <= end; i += 2) {
        int s0 = g_col[i], s1 = g_col[i + 1];
        uint2 u0 = reinterpret_cast<const uint2*>(h + (size_t)s0 * 64)[hl];
        uint2 u1 = reinterpret_cast<const uint2*>(h + (size_t)s1 * 64)[hl];
        float2 p0 = __bfloat1622float2(u2bf2(u0.x));
        float2 p1 = __bfloat1622float2(u2bf2(u0.y));
        float2 q0 = __bfloat1622float2(u2bf2(u1.x));
        float2 q1 = __bfloat1622float2(u2bf2(u1.y));
        a0.x += p0.x; a0.y += p0.y; a0.z += p1.x; a0.w += p1.y;
        a1.x += q0.x; a1.y += q0.y; a1.z += q1.x; a1.w += q1.y;
    }
    if (i < end) {
        int s0 = g_col[i];
        uint2 u0 = reinterpret_cast<const uint2*>(h + (size_t)s0 * 64)[hl];
        float2 p0 = __bfloat1622float2(u2bf2(u0.x));
        float2 p1 = __bfloat1622float2(u2bf2(u0.y));
        a0.x += p0.x; a0.y += p0.y; a0.z += p1.x; a0.w += p1.y;
    }
    if (valid) {
        uint2 us = reinterpret_cast<const uint2*>(h + (size_t)w * 64)[hl];
        float2 p0 = __bfloat1622float2(u2bf2(us.x));
        float2 p1 = __bfloat1622float2(u2bf2(us.y));
        a0.x += p0.x; a0.y += p0.y; a0.z += p1.x; a0.w += p1.y;

        float4 bb = reinterpret_cast<const float4*>(bias)[hl];
        float o0 = fmaxf(dd * (a0.x + a1.x) + bb.x, 0.f);
        float o1 = fmaxf(dd * (a0.y + a1.y) + bb.y, 0.f);
        float o2 = fmaxf(dd * (a0.z + a1.z) + bb.z, 0.f);
        float o3 = fmaxf(dd * (a0.w + a1.w) + bb.w, 0.f);
        atomicAdd(&sp[hl * 4 + 0], o0);
        atomicAdd(&sp[hl * 4 + 1], o1);
        atomicAdd(&sp[hl * 4 + 2], o2);
        atomicAdd(&sp[hl * 4 + 3], o3);
    }
    __syncthreads();
    if (tid < 64) atomicAdd(&g_pooled[tid], sp[tid]);
}

// ---------------- classifier + softmax --------------------------------------
__global__ void cls_kernel(const float* __restrict__ Wc1, const float* __restrict__ bc1,
                           const float* __restrict__ Wc2, const float* __restrict__ bc2,
                           float* __restrict__ out, float invN) {
    __shared__ float z[32];
    int t = threadIdx.x;
    if (t < 32) {
        float a = bc1[t];
        for (int i = 0; i < 64; i++)
            a = fmaf(g_pooled[i] * invN, Wc1[i * 32 + t], a);
        z[t] = fmaxf(a, 0.f);
    }
    __syncthreads();
    if (t == 0) {
        float l0 = bc2[0], l1 = bc2[1];
        for (int j = 0; j < 32; j++) {
            l0 = fmaf(z[j], Wc2[j * 2 + 0], l0);
            l1 = fmaf(z[j], Wc2[j * 2 + 1], l1);
        }
        float m = fmaxf(l0, l1);
        float e0 = expf(l0 - m), e1 = expf(l1 - m);
        float s = e0 + e1;
        out[0] = e0 / s;
        out[1] = e1 / s;
    }
}

// ---------------- launch -----------------------------------------------------
extern "C" void kernel_launch(void* const* d_in, const int* in_sizes, int n_in,
                              void* d_out, int out_size) {
    const float* x   = (const float*)d_in[0];
    const int*   ei  = (const int*)d_in[1];
    const float* W1  = (const float*)d_in[2];
    const float* b1  = (const float*)d_in[3];
    const float* W2  = (const float*)d_in[4];
    const float* b2  = (const float*)d_in[5];
    const float* W3  = (const float*)d_in[6];
    const float* b3  = (const float*)d_in[7];
    const float* Wc1 = (const float*)d_in[8];
    const float* bc1 = (const float*)d_in[9];
    const float* Wc2 = (const float*)d_in[10];
    const float* bc2 = (const float*)d_in[11];
    float* out = (float*)d_out;

    int n = in_sizes[0] / 64;
    int e = in_sizes[1] / 2;
    const int* src = ei;
    const int* dst = ei + e;
    int nb = (n + SCAN_CHUNK - 1) / SCAN_CHUNK;

    __nv_bfloat16* A;  cudaGetSymbolAddress((void**)&A, g_hA);
    __nv_bfloat16* B;  cudaGetSymbolAddress((void**)&B, g_hB);
    int*   edeg;   cudaGetSymbolAddress((void**)&edeg, g_edeg);
    float* pooled; cudaGetSymbolAddress((void**)&pooled, g_pooled);

    // host-side resources, created once on the (uncaptured) correctness call
    static cudaStream_t side = nullptr;
    static cudaEvent_t evA = nullptr, evC = nullptr;
    if (side == nullptr) {
        cudaStreamCreateWithFlags(&side, cudaStreamNonBlocking);
        cudaEventCreateWithFlags(&evA, cudaEventDisableTiming);
        cudaEventCreateWithFlags(&evC, cudaEventDisableTiming);
    }

    // graph prep (default stream)
    cudaMemsetAsync(edeg, 0, (size_t)n * sizeof(int), 0);
    cudaMemsetAsync(pooled, 0, 64 * sizeof(float), 0);
    degree_kernel<<<1024, 256>>>(dst, e);
    scanA_kernel<<<nb, 256>>>(n);                 // deg sums + dis

    // fork: cvt (needs only dis) overlaps scanC + fill on the side stream
    cudaEventRecord(evA, 0);
    cudaStreamWaitEvent(side, evA, 0);
    cvt_kernel<<<1024, 256, 0, side>>>(x, A, n * 8);   // x -> dis-prescaled bf16 (T0)
    cudaEventRecord(evC, side);

    scanC_kernel<<<nb, 256>>>(nb, n);             // offsets
    fill_kernel<<<1024, 256>>>(src, dst, e);      // CSR (in-place cursors)
    cudaStreamWaitEvent(0, evC, 0);               // join before layer 1

    int gg = (n + 127) / 128;
    int ga2 = (n + 15) / 16;  // 2 nodes/warp, 8 warps/block
    // layer 1 FUSED: agg(T0) + gemm1(relu(a@W1+b1)*dis) -> T1 (prescaled)
    agg_gemm1_kernel<<<gg, 512>>>(A, W1, b1, B, n);
    // layer 2: gemm2(T1@W2) = messages ; agg2: relu(dd*sum+b2)*dd -> T2 (prescaled)
    gemm_tc_kernel<128, 128, false, false><<<gg, 256>>>(B, W2, nullptr, A, n);
    agg128_kernel<<<ga2, 256>>>(A, b2, B, n);
    // layer 3: gemm3(T2@W3) = messages ; agg+pool
    gemm_tc_kernel<128, 64, false, false><<<gg, 256>>>(B, W3, nullptr, A, n);
    agg_pool_kernel<<<ga2, 256>>>(A, b3, n);

    cls_kernel<<<1, 64>>>(Wc1, bc1, Wc2, bc2, out, 1.0f / (float)n);
}

// round 17
// speedup vs baseline: 1.0741x; 1.0136x over previous
#include <cuda_runtime.h>
#include <cuda_bf16.h>
#include <math.h>

#define MAXN 100000
#define MAXE 1600000
#define SCAN_CHUNK 1024

// ---------------- scratch ---------------------------------------------------
__device__ __align__(16) int   g_edeg[MAXN];
__device__ __align__(16) float g_dis[MAXN];
__device__ __align__(16) int   g_off[MAXN + 1];   // after fill: inclusive ends
__device__ __align__(16) int   g_col[MAXE];
__device__ __align__(16) int   g_bsum[128];
__device__ __align__(16) __nv_bfloat16 g_hA[(size_t)MAXN * 128];
__device__ __align__(16) __nv_bfloat16 g_hB[(size_t)MAXN * 128];
__device__ __align__(16) float g_pooled[64];

__device__ __forceinline__ __nv_bfloat162 u2bf2(unsigned u) {
    return *reinterpret_cast<__nv_bfloat162*>(&u);
}

// ---------------- degree histogram over dst (int4 vectorized) ---------------
__global__ void degree_kernel(const int* __restrict__ dst, int e) {
    int i = blockIdx.x * blockDim.x + threadIdx.x;
    int stride = gridDim.x * blockDim.x;
    int e4 = e >> 2;
    for (int k = i; k < e4; k += stride) {
        int4 d = reinterpret_cast<const int4*>(dst)[k];
        atomicAdd(&g_edeg[d.x], 1);
        atomicAdd(&g_edeg[d.y], 1);
        atomicAdd(&g_edeg[d.z], 1);
        atomicAdd(&g_edeg[d.w], 1);
    }
    if (i < (e & 3)) atomicAdd(&g_edeg[dst[e4 * 4 + i]], 1);
}

// ---------------- scan phase A: per-block sums + dis ------------------------
__global__ void scanA_kernel(int n) {
    __shared__ int ssum[8];
    int base = blockIdx.x * SCAN_CHUNK + threadIdx.x * 4;
    int s = 0;
#pragma unroll
    for (int j = 0; j < 4; j++) {
        int idx = base + j;
        if (idx < n) {
            int d = g_edeg[idx];
            s += d;
            g_dis[idx] = rsqrtf((float)(d + 1));
        }
    }
#pragma unroll
    for (int o = 16; o > 0; o >>= 1) s += __shfl_down_sync(0xffffffffu, s, o);
    if ((threadIdx.x & 31) == 0) ssum[threadIdx.x >> 5] = s;
    __syncthreads();
    if (threadIdx.x == 0) {
        int t = 0;
#pragma unroll
        for (int w = 0; w < 8; w++) t += ssum[w];
        g_bsum[blockIdx.x] = t;
    }
}

// ---------------- x -> bf16, prescaled by dis[row] (vectorized x8) ----------
__global__ void cvt_kernel(const float* __restrict__ x, __nv_bfloat16* __restrict__ o,
                           int total8) {
    int i = blockIdx.x * blockDim.x + threadIdx.x;
    int stride = gridDim.x * blockDim.x;
    for (int k = i; k < total8; k += stride) {
        int base = k * 8;
        float dd = g_dis[base >> 6];
        float4 a = *reinterpret_cast<const float4*>(x + base);
        float4 b = *reinterpret_cast<const float4*>(x + base + 4);
        __nv_bfloat162 p0 = __floats2bfloat162_rn(a.x * dd, a.y * dd);
        __nv_bfloat162 p1 = __floats2bfloat162_rn(a.z * dd, a.w * dd);
        __nv_bfloat162 p2 = __floats2bfloat162_rn(b.x * dd, b.y * dd);
        __nv_bfloat162 p3 = __floats2bfloat162_rn(b.z * dd, b.w * dd);
        uint4 r;
        r.x = *reinterpret_cast<unsigned*>(&p0);
        r.y = *reinterpret_cast<unsigned*>(&p1);
        r.z = *reinterpret_cast<unsigned*>(&p2);
        r.w = *reinterpret_cast<unsigned*>(&p3);
        *reinterpret_cast<uint4*>(o + base) = r;
    }
}

// ---------------- scan phase C (with inline block-sum scan) -----------------
__global__ void scanC_kernel(int nb, int n) {
    __shared__ int sb[128];
    __shared__ int sh[256];
    int t = threadIdx.x;
    if (t < 128) sb[t] = (t < nb) ? g_bsum[t] : 0;
    __syncthreads();
#pragma unroll
    for (int o = 1; o < 128; o <<= 1) {
        int u = (t >= o && t < 128) ? sb[t - o] : 0;
        __syncthreads();
        if (t < 128) sb[t] += u;
        __syncthreads();
    }
    int boff = (blockIdx.x == 0) ? 0 : sb[blockIdx.x - 1];
    if (blockIdx.x == 0 && t == 0) g_off[n] = sb[127];

    int base = blockIdx.x * SCAN_CHUNK + t * 4;
    int d[4];
    int s = 0;
#pragma unroll
    for (int j = 0; j < 4; j++) {
        int idx = base + j;
        d[j] = (idx < n) ? g_edeg[idx] : 0;
        s += d[j];
    }
    sh[t] = s;
    __syncthreads();
#pragma unroll
    for (int o = 1; o < 256; o <<= 1) {
        int u = (t >= o) ? sh[t - o] : 0;
        __syncthreads();
        sh[t] += u;
        __syncthreads();
    }
    int run = boff + sh[t] - s;
#pragma unroll
    for (int j = 0; j < 4; j++) {
        int idx = base + j;
        if (idx < n) g_off[idx] = run;
        run += d[j];
    }
}

// ---------------- CSR fill (in-place cursor on g_off, int4 vectorized) ------
__global__ void fill_kernel(const int* __restrict__ src,
                            const int* __restrict__ dst, int e) {
    int i = blockIdx.x * blockDim.x + threadIdx.x;
    int stride = gridDim.x * blockDim.x;
    int e4 = e >> 2;
    for (int k = i; k < e4; k += stride) {
        int4 d = reinterpret_cast<const int4*>(dst)[k];
        int4 s = reinterpret_cast<const int4*>(src)[k];
        g_col[atomicAdd(&g_off[d.x], 1)] = s.x;
        g_col[atomicAdd(&g_off[d.y], 1)] = s.y;
        g_col[atomicAdd(&g_off[d.z], 1)] = s.z;
        g_col[atomicAdd(&g_off[d.w], 1)] = s.w;
    }
    if (i < (e & 3)) {
        int k = e4 * 4 + i;
        g_col[atomicAdd(&g_off[dst[k]], 1)] = src[k];
    }
}

// ---------------- helpers ----------------------------------------------------
__device__ __forceinline__ unsigned smem_u32(const void* p) {
    return (unsigned)__cvta_generic_to_shared(p);
}
__device__ __forceinline__ void ldsm_x4(unsigned& r0, unsigned& r1, unsigned& r2,
                                        unsigned& r3, unsigned addr) {
    asm volatile("ldmatrix.sync.aligned.m8n8.x4.shared.b16 {%0,%1,%2,%3}, [%4];\n"
                 : "=r"(r0), "=r"(r1), "=r"(r2), "=r"(r3) : "r"(addr));
}
__device__ __forceinline__ void ldsm_x4_t(unsigned& r0, unsigned& r1, unsigned& r2,
                                          unsigned& r3, unsigned addr) {
    asm volatile("ldmatrix.sync.aligned.m8n8.x4.trans.shared.b16 {%0,%1,%2,%3}, [%4];\n"
                 : "=r"(r0), "=r"(r1), "=r"(r2), "=r"(r3) : "r"(addr));
}
__device__ __forceinline__ void mma_bf16(float* d, const unsigned* a, const unsigned* b) {
    asm volatile(
        "mma.sync.aligned.m16n8k16.row.col.f32.bf16.bf16.f32 "
        "{%0,%1,%2,%3}, {%4,%5,%6,%7}, {%8,%9}, {%0,%1,%2,%3};\n"
        : "+f"(d[0]), "+f"(d[1]), "+f"(d[2]), "+f"(d[3])
        : "r"(a[0]), "r"(a[1]), "r"(a[2]), "r"(a[3]), "r"(b[0]), "r"(b[1]));
}

// ---------------- FUSED layer 1: agg(width 64) -> GEMM(64->128)+bias+relu*dis
__global__ void __launch_bounds__(512, 2)
agg_gemm1_kernel(const __nv_bfloat16* __restrict__ h,
                 const float* __restrict__ W,
                 const float* __restrict__ bias,
                 __nv_bfloat16* __restrict__ C, int n) {
    constexpr int KC = 64;
    constexpr int HOUT = 128;
    constexpr int SA_S = KC + 8;   // 72
    constexpr int SW_S = HOUT + 8; // 136
    __shared__ __nv_bfloat16 sA[128 * SA_S];
    __shared__ __nv_bfloat16 sW[KC * SW_S];

    int tid = threadIdx.x;
    int wid = tid >> 5;
    int lane = tid & 31;
    int rowBase = blockIdx.x * 128;

    constexpr int WC4 = HOUT / 4;
    for (int i = tid; i < KC * WC4; i += 512) {
        int k = i / WC4, c4 = i % WC4;
        float4 w = *reinterpret_cast<const float4*>(W + (size_t)k * HOUT + c4 * 4);
        __nv_bfloat162 p0 = __floats2bfloat162_rn(w.x, w.y);
        __nv_bfloat162 p1 = __floats2bfloat162_rn(w.z, w.w);
        uint2 pk;
        pk.x = *reinterpret_cast<unsigned*>(&p0);
        pk.y = *reinterpret_cast<unsigned*>(&p1);
        *reinterpret_cast<uint2*>(&sW[k * SW_S + c4 * 4]) = pk;
    }

    int half = lane >> 4;
    int hl   = lane & 15;
#pragma unroll
    for (int p = 0; p < 4; p++) {
        int r = p * 32 + wid * 2 + half;
        int w = rowBase + r;
        uint2 res = make_uint2(0u, 0u);
        if (w < n) {
            int beg = (w == 0) ? 0 : g_off[w - 1];
            int end = g_off[w];
            float dd = g_dis[w];
            float4 a0 = make_float4(0.f, 0.f, 0.f, 0.f);
            float4 a1 = make_float4(0.f, 0.f, 0.f, 0.f);
            int i = beg;
            for (; i + 2 <= end; i += 2) {
                int s0 = g_col[i], s1 = g_col[i + 1];
                uint2 u0 = reinterpret_cast<const uint2*>(h + (size_t)s0 * 64)[hl];
                uint2 u1 = reinterpret_cast<const uint2*>(h + (size_t)s1 * 64)[hl];
                float2 p0 = __bfloat1622float2(u2bf2(u0.x));
                float2 p1 = __bfloat1622float2(u2bf2(u0.y));
                float2 q0 = __bfloat1622float2(u2bf2(u1.x));
                float2 q1 = __bfloat1622float2(u2bf2(u1.y));
                a0.x += p0.x; a0.y += p0.y; a0.z += p1.x; a0.w += p1.y;
                a1.x += q0.x; a1.y += q0.y; a1.z += q1.x; a1.w += q1.y;
            }
            if (i < end) {
                int s0 = g_col[i];
                uint2 u0 = reinterpret_cast<const uint2*>(h + (size_t)s0 * 64)[hl];
                float2 p0 = __bfloat1622float2(u2bf2(u0.x));
                float2 p1 = __bfloat1622float2(u2bf2(u0.y));
                a0.x += p0.x; a0.y += p0.y; a0.z += p1.x; a0.w += p1.y;
            }
            uint2 us = reinterpret_cast<const uint2*>(h + (size_t)w * 64)[hl];
            float2 p0 = __bfloat1622float2(u2bf2(us.x));
            float2 p1 = __bfloat1622float2(u2bf2(us.y));
            a0.x += p0.x; a0.y += p0.y; a0.z += p1.x; a0.w += p1.y;

            __nv_bfloat162 r0 = __floats2bfloat162_rn(dd * (a0.x + a1.x),
                                                      dd * (a0.y + a1.y));
            __nv_bfloat162 r1 = __floats2bfloat162_rn(dd * (a0.z + a1.z),
                                                      dd * (a0.w + a1.w));
            res.x = *reinterpret_cast<unsigned*>(&r0);
            res.y = *reinterpret_cast<unsigned*>(&r1);
        }
        *reinterpret_cast<uint2*>(&sA[r * SA_S + hl * 4]) = res;
    }
    __syncthreads();

    int stripe = wid >> 1;
    int nh = wid & 1;
    int m0 = stripe * 16;
    float acc[8][4];
#pragma unroll
    for (int t = 0; t < 8; t++)
#pragma unroll
        for (int j = 0; j < 4; j++) acc[t][j] = 0.0f;

#pragma unroll
    for (int ks = 0; ks < 4; ks++) {
        int k0 = ks * 16;
        unsigned a[4];
        {
            int r = m0 + (lane & 15);
            int c = k0 + (lane >> 4) * 8;
            ldsm_x4(a[0], a[1], a[2], a[3], smem_u32(&sA[r * SA_S + c]));
        }
#pragma unroll
        for (int nt2 = 0; nt2 < 4; nt2++) {
            int n0 = nh * 64 + nt2 * 16;
            unsigned b[4];
            int rk = k0 + (lane & 15);
            int cn = n0 + (lane >> 4) * 8;
            ldsm_x4_t(b[0], b[1], b[2], b[3], smem_u32(&sW[rk * SW_S + cn]));
            mma_bf16(acc[2 * nt2], a, b);
            mma_bf16(acc[2 * nt2 + 1], a, b + 2);
        }
    }

    int r = lane >> 2;
    int c2 = (lane & 3) * 2;
    int row0 = rowBase + m0 + r;
    int row1 = row0 + 8;
    float ds0 = (row0 < n) ? g_dis[row0] : 0.f;
    float ds1 = (row1 < n) ? g_dis[row1] : 0.f;
#pragma unroll
    for (int t = 0; t < 8; t++) {
        int col = nh * 64 + t * 8 + c2;
        float b0 = bias[col], b1 = bias[col + 1];
        float v0 = fmaxf(acc[t][0] + b0, 0.f) * ds0;
        float v1 = fmaxf(acc[t][1] + b1, 0.f) * ds0;
        float v2 = fmaxf(acc[t][2] + b0, 0.f) * ds1;
        float v3 = fmaxf(acc[t][3] + b1, 0.f) * ds1;
        if (row0 < n) {
            __nv_bfloat162 p = __floats2bfloat162_rn(v0, v1);
            *reinterpret_cast<unsigned*>(C + (size_t)row0 * 128 + col) =
                *reinterpret_cast<unsigned*>(&p);
        }
        if (row1 < n) {
            __nv_bfloat162 p = __floats2bfloat162_rn(v2, v3);
            *reinterpret_cast<unsigned*>(C + (size_t)row1 * 128 + col) =
                *reinterpret_cast<unsigned*>(&p);
        }
    }
}

// ---------------- FUSED layers 2b+3a: agg128(+b2,relu,*dd) -> GEMM(128->64) -
// Dynamic smem: sA 128x136 bf16 (34816 B) + sW 128x72 bf16 (18432 B) = 53248 B.
// Phase 1 = agg128 loop writing bf16 rows straight into sA; phase 2 = mma,
// 2 warps per 16-row stripe, each a 32-col N-half; output = layer-3 messages.
__global__ void __launch_bounds__(512, 2)
agg_gemm3_kernel(const __nv_bfloat16* __restrict__ h,
                 const float* __restrict__ W,
                 const float* __restrict__ bias,
                 __nv_bfloat16* __restrict__ C, int n) {
    constexpr int K = 128;
    constexpr int HOUT = 64;
    constexpr int SA_S = K + 8;    // 136 (272 B row, 16B-aligned)
    constexpr int SW_S = HOUT + 8; // 72  (144 B row, 16B-aligned)
    extern __shared__ __nv_bfloat16 smem[];
    __nv_bfloat16* sA = smem;                    // 128 * 136
    __nv_bfloat16* sW = smem + 128 * SA_S;       // 128 * 72

    int tid = threadIdx.x;
    int wid = tid >> 5;
    int lane = tid & 31;
    int rowBase = blockIdx.x * 128;

    // load W3 (128 x 64) into sW
    constexpr int WC4 = HOUT / 4;
    for (int i = tid; i < K * WC4; i += 512) {
        int k = i / WC4, c4 = i % WC4;
        float4 w = *reinterpret_cast<const float4*>(W + (size_t)k * HOUT + c4 * 4);
        __nv_bfloat162 p0 = __floats2bfloat162_rn(w.x, w.y);
        __nv_bfloat162 p1 = __floats2bfloat162_rn(w.z, w.w);
        uint2 pk;
        pk.x = *reinterpret_cast<unsigned*>(&p0);
        pk.y = *reinterpret_cast<unsigned*>(&p1);
        *reinterpret_cast<uint2*>(&sW[k * SW_S + c4 * 4]) = pk;
    }

    // phase 1: aggregate 128 nodes (2 nodes/warp x 4 passes) into sA
    int half = lane >> 4;
    int hl   = lane & 15;
#define ACCU4(AL, AH, U) { \
        float2 t0 = __bfloat1622float2(u2bf2((U).x)); \
        float2 t1 = __bfloat1622float2(u2bf2((U).y)); \
        float2 t2 = __bfloat1622float2(u2bf2((U).z)); \
        float2 t3 = __bfloat1622float2(u2bf2((U).w)); \
        AL.x += t0.x; AL.y += t0.y; AL.z += t1.x; AL.w += t1.y; \
        AH.x += t2.x; AH.y += t2.y; AH.z += t3.x; AH.w += t3.y; }
#pragma unroll
    for (int p = 0; p < 4; p++) {
        int r = p * 32 + wid * 2 + half;
        int w = rowBase + r;
        uint4 res = make_uint4(0u, 0u, 0u, 0u);
        if (w < n) {
            int beg = (w == 0) ? 0 : g_off[w - 1];
            int end = g_off[w];
            float dd = g_dis[w];
            float4 aL0 = make_float4(0.f, 0.f, 0.f, 0.f), aH0 = aL0;
            float4 aL1 = aL0, aH1 = aL0;
            int i = beg;
            for (; i + 4 <= end; i += 4) {
                int s0 = g_col[i], s1 = g_col[i + 1], s2 = g_col[i + 2], s3 = g_col[i + 3];
                uint4 u0 = reinterpret_cast<const uint4*>(h + (size_t)s0 * 128)[hl];
                uint4 u1 = reinterpret_cast<const uint4*>(h + (size_t)s1 * 128)[hl];
                uint4 u2 = reinterpret_cast<const uint4*>(h + (size_t)s2 * 128)[hl];
                uint4 u3 = reinterpret_cast<const uint4*>(h + (size_t)s3 * 128)[hl];
                ACCU4(aL0, aH0, u0)
                ACCU4(aL1, aH1, u1)
                ACCU4(aL0, aH0, u2)
                ACCU4(aL1, aH1, u3)
            }
            for (; i < end; i++) {
                uint4 u0 = reinterpret_cast<const uint4*>(h + (size_t)g_col[i] * 128)[hl];
                ACCU4(aL0, aH0, u0)
            }
            uint4 us = reinterpret_cast<const uint4*>(h + (size_t)w * 128)[hl];
            ACCU4(aL0, aH0, us)

            float4 bb0 = reinterpret_cast<const float4*>(bias)[hl * 2];
            float4 bb1 = reinterpret_cast<const float4*>(bias)[hl * 2 + 1];
            float o0 = fmaxf(dd * (aL0.x + aL1.x) + bb0.x, 0.f) * dd;
            float o1 = fmaxf(dd * (aL0.y + aL1.y) + bb0.y, 0.f) * dd;
            float o2 = fmaxf(dd * (aL0.z + aL1.z) + bb0.z, 0.f) * dd;
            float o3 = fmaxf(dd * (aL0.w + aL1.w) + bb0.w, 0.f) * dd;
            float o4 = fmaxf(dd * (aH0.x + aH1.x) + bb1.x, 0.f) * dd;
            float o5 = fmaxf(dd * (aH0.y + aH1.y) + bb1.y, 0.f) * dd;
            float o6 = fmaxf(dd * (aH0.z + aH1.z) + bb1.z, 0.f) * dd;
            float o7 = fmaxf(dd * (aH0.w + aH1.w) + bb1.w, 0.f) * dd;
            __nv_bfloat162 r0 = __floats2bfloat162_rn(o0, o1);
            __nv_bfloat162 r1 = __floats2bfloat162_rn(o2, o3);
            __nv_bfloat162 r2 = __floats2bfloat162_rn(o4, o5);
            __nv_bfloat162 r3 = __floats2bfloat162_rn(o6, o7);
            res.x = *reinterpret_cast<unsigned*>(&r0);
            res.y = *reinterpret_cast<unsigned*>(&r1);
            res.z = *reinterpret_cast<unsigned*>(&r2);
            res.w = *reinterpret_cast<unsigned*>(&r3);
        }
        *reinterpret_cast<uint4*>(&sA[r * SA_S + hl * 8]) = res;
    }
#undef ACCU4
    __syncthreads();

    // phase 2: mma K=128 -> HOUT=64; 2 warps per 16-row stripe, 32-col halves
    int stripe = wid >> 1;
    int nh = wid & 1;
    int m0 = stripe * 16;
    float acc[4][4];
#pragma unroll
    for (int t = 0; t < 4; t++)
#pragma unroll
        for (int j = 0; j < 4; j++) acc[t][j] = 0.0f;

#pragma unroll
    for (int ks = 0; ks < 8; ks++) {
        int k0 = ks * 16;
        unsigned a[4];
        {
            int r = m0 + (lane & 15);
            int c = k0 + (lane >> 4) * 8;
            ldsm_x4(a[0], a[1], a[2], a[3], smem_u32(&sA[r * SA_S + c]));
        }
#pragma unroll
        for (int nt2 = 0; nt2 < 2; nt2++) {
            int n0 = nh * 32 + nt2 * 16;
            unsigned b[4];
            int rk = k0 + (lane & 15);
            int cn = n0 + (lane >> 4) * 8;
            ldsm_x4_t(b[0], b[1], b[2], b[3], smem_u32(&sW[rk * SW_S + cn]));
            mma_bf16(acc[2 * nt2], a, b);
            mma_bf16(acc[2 * nt2 + 1], a, b + 2);
        }
    }

    // epilogue: store layer-3 messages (no bias, no scale)
    int r = lane >> 2;
    int c2 = (lane & 3) * 2;
    int row0 = rowBase + m0 + r;
    int row1 = row0 + 8;
#pragma unroll
    for (int t = 0; t < 4; t++) {
        int col = nh * 32 + t * 8 + c2;
        if (row0 < n) {
            __nv_bfloat162 p = __floats2bfloat162_rn(acc[t][0], acc[t][1]);
            *reinterpret_cast<unsigned*>(C + (size_t)row0 * 64 + col) =
                *reinterpret_cast<unsigned*>(&p);
        }
        if (row1 < n) {
            __nv_bfloat162 p = __floats2bfloat162_rn(acc[t][2], acc[t][3]);
            *reinterpret_cast<unsigned*>(C + (size_t)row1 * 64 + col) =
                *reinterpret_cast<unsigned*>(&p);
        }
    }
}

// ---------------- tensor-core GEMM (layer 2) ---------------------------------
template <int K, int HOUT, bool BIASRELU, bool DISSCALE>
__global__ void __launch_bounds__(256, 2)
gemm_tc_kernel(const __nv_bfloat16* __restrict__ A,
               const float* __restrict__ W,
               const float* __restrict__ bias,
               __nv_bfloat16* __restrict__ C, int n) {
    constexpr int KC = 64;
    constexpr int SA_S = KC + 8;
    constexpr int SW_S = HOUT + 8;
    constexpr int NT = HOUT / 8;
    __shared__ __nv_bfloat16 sA[128 * SA_S];
    __shared__ __nv_bfloat16 sW[KC * SW_S];

    int tid = threadIdx.x;
    int wid = tid >> 5;
    int lane = tid & 31;
    int rowBase = blockIdx.x * 128;
    int m0 = wid * 16;

    float acc[NT][4];
#pragma unroll
    for (int t = 0; t < NT; t++)
#pragma unroll
        for (int j = 0; j < 4; j++) acc[t][j] = 0.0f;

    for (int kc = 0; kc < K; kc += KC) {
        constexpr int SEGS = KC / 8;
        for (int i = tid; i < 128 * SEGS; i += 256) {
            int r = i / SEGS, sg = i % SEGS;
            int row = rowBase + r;
            uint4 v = make_uint4(0, 0, 0, 0);
            if (row < n)
                v = *reinterpret_cast<const uint4*>(A + (size_t)row * K + kc + sg * 8);
            *reinterpret_cast<uint4*>(&sA[r * SA_S + sg * 8]) = v;
        }
        constexpr int WC4 = HOUT / 4;
        for (int i = tid; i < KC * WC4; i += 256) {
            int k = i / WC4, c4 = i % WC4;
            float4 w = *reinterpret_cast<const float4*>(W + (size_t)(kc + k) * HOUT + c4 * 4);
            __nv_bfloat162 p0 = __floats2bfloat162_rn(w.x, w.y);
            __nv_bfloat162 p1 = __floats2bfloat162_rn(w.z, w.w);
            uint2 pk;
            pk.x = *reinterpret_cast<unsigned*>(&p0);
            pk.y = *reinterpret_cast<unsigned*>(&p1);
            *reinterpret_cast<uint2*>(&sW[k * SW_S + c4 * 4]) = pk;
        }
        __syncthreads();

#pragma unroll
        for (int ks = 0; ks < KC / 16; ks++) {
            int k0 = ks * 16;
            unsigned a[4];
            {
                int r = m0 + (lane & 15);
                int c = k0 + (lane >> 4) * 8;
                ldsm_x4(a[0], a[1], a[2], a[3], smem_u32(&sA[r * SA_S + c]));
            }
#pragma unroll
            for (int nt2 = 0; nt2 < NT / 2; nt2++) {
                int n0 = nt2 * 16;
                unsigned b[4];
                int rk = k0 + (lane & 15);
                int cn = n0 + (lane >> 4) * 8;
                ldsm_x4_t(b[0], b[1], b[2], b[3], smem_u32(&sW[rk * SW_S + cn]));
                mma_bf16(acc[2 * nt2], a, b);
                mma_bf16(acc[2 * nt2 + 1], a, b + 2);
            }
        }
        __syncthreads();
    }

    int r = lane >> 2;
    int c2 = (lane & 3) * 2;
    int row0 = rowBase + m0 + r;
    int row1 = row0 + 8;
    float ds0 = 1.f, ds1 = 1.f;
    if (DISSCALE) {
        if (row0 < n) ds0 = g_dis[row0];
        if (row1 < n) ds1 = g_dis[row1];
    }
#pragma unroll
    for (int t = 0; t < NT; t++) {
        int col = t * 8 + c2;
        float v0 = acc[t][0], v1 = acc[t][1], v2 = acc[t][2], v3 = acc[t][3];
        if (BIASRELU) {
            float b0 = bias[col], b1 = bias[col + 1];
            v0 = fmaxf(v0 + b0, 0.f); v1 = fmaxf(v1 + b1, 0.f);
            v2 = fmaxf(v2 + b0, 0.f); v3 = fmaxf(v3 + b1, 0.f);
        }
        if (DISSCALE) { v0 *= ds0; v1 *= ds0; v2 *= ds1; v3 *= ds1; }
        if (row0 < n) {
            __nv_bfloat162 p = __floats2bfloat162_rn(v0, v1);
            *reinterpret_cast<unsigned*>(C + (size_t)row0 * HOUT + col) =
                *reinterpret_cast<unsigned*>(&p);
        }
        if (row1 < n) {
            __nv_bfloat162 p = __floats2bfloat162_rn(v2, v3);
            *reinterpret_cast<unsigned*>(C + (size_t)row1 * HOUT + col) =
                *reinterpret_cast<unsigned*>(&p);
        }
    }
}

// ---------------- layer-3 agg (2 nodes/warp, width 64) + mean pool ----------
__global__ void agg_pool_kernel(const __nv_bfloat16* __restrict__ h,
                                const float* __restrict__ bias, int n) {
    __shared__ float sp[64];
    int tid = threadIdx.x;
    if (tid < 64) sp[tid] = 0.f;
    __syncthreads();

    int warp = (blockIdx.x * blockDim.x + tid) >> 5;
    int lane = tid & 31;
    int half = lane >> 4;
    int hl   = lane & 15;
    int w = warp * 2 + half;
    bool valid = w < n;

    int beg = 0, end = 0;
    float dd = 0.f;
    if (valid) {
        beg = (w == 0) ? 0 : g_off[w - 1];
        end = g_off[w];
        dd  = g_dis[w];
    }

    float4 a0 = make_float4(0.f, 0.f, 0.f, 0.f);
    float4 a1 = make_float4(0.f, 0.f, 0.f, 0.f);
    int i = beg;
    for (; i + 2 <= end; i += 2) {
        int s0 = g_col[i], s1 = g_col[i + 1];
        uint2 u0 = reinterpret_cast<const uint2*>(h + (size_t)s0 * 64)[hl];
        uint2 u1 = reinterpret_cast<const uint2*>(h + (size_t)s1 * 64)[hl];
        float2 p0 = __bfloat1622float2(u2bf2(u0.x));
        float2 p1 = __bfloat1622float2(u2bf2(u0.y));
        float2 q0 = __bfloat1622float2(u2bf2(u1.x));
        float2 q1 = __bfloat1622float2(u2bf2(u1.y));
        a0.x += p0.x; a0.y += p0.y; a0.z += p1.x; a0.w += p1.y;
        a1.x += q0.x; a1.y += q0.y; a1.z += q1.x; a1.w += q1.y;
    }
    if (i < end) {
        int s0 = g_col[i];
        uint2 u0 = reinterpret_cast<const uint2*>(h + (size_t)s0 * 64)[hl];
        float2 p0 = __bfloat1622float2(u2bf2(u0.x));
        float2 p1 = __bfloat1622float2(u2bf2(u0.y));
        a0.x += p0.x; a0.y += p0.y; a0.z += p1.x; a0.w += p1.y;
    }
    if (valid) {
        uint2 us = reinterpret_cast<const uint2*>(h + (size_t)w * 64)[hl];
        float2 p0 = __bfloat1622float2(u2bf2(us.x));
        float2 p1 = __bfloat1622float2(u2bf2(us.y));
        a0.x += p0.x; a0.y += p0.y; a0.z += p1.x; a0.w += p1.y;

        float4 bb = reinterpret_cast<const float4*>(bias)[hl];
        float o0 = fmaxf(dd * (a0.x + a1.x) + bb.x, 0.f);
        float o1 = fmaxf(dd * (a0.y + a1.y) + bb.y, 0.f);
        float o2 = fmaxf(dd * (a0.z + a1.z) + bb.z, 0.f);
        float o3 = fmaxf(dd * (a0.w + a1.w) + bb.w, 0.f);
        atomicAdd(&sp[hl * 4 + 0], o0);
        atomicAdd(&sp[hl * 4 + 1], o1);
        atomicAdd(&sp[hl * 4 + 2], o2);
        atomicAdd(&sp[hl * 4 + 3], o3);
    }
    __syncthreads();
    if (tid < 64) atomicAdd(&g_pooled[tid], sp[tid]);
}

// ---------------- classifier + softmax --------------------------------------
__global__ void cls_kernel(const float* __restrict__ Wc1, const float* __restrict__ bc1,
                           const float* __restrict__ Wc2, const float* __restrict__ bc2,
                           float* __restrict__ out, float invN) {
    __shared__ float z[32];
    int t = threadIdx.x;
    if (t < 32) {
        float a = bc1[t];
        for (int i = 0; i < 64; i++)
            a = fmaf(g_pooled[i] * invN, Wc1[i * 32 + t], a);
        z[t] = fmaxf(a, 0.f);
    }
    __syncthreads();
    if (t == 0) {
        float l0 = bc2[0], l1 = bc2[1];
        for (int j = 0; j < 32; j++) {
            l0 = fmaf(z[j], Wc2[j * 2 + 0], l0);
            l1 = fmaf(z[j], Wc2[j * 2 + 1], l1);
        }
        float m = fmaxf(l0, l1);
        float e0 = expf(l0 - m), e1 = expf(l1 - m);
        float s = e0 + e1;
        out[0] = e0 / s;
        out[1] = e1 / s;
    }
}

// ---------------- launch -----------------------------------------------------
extern "C" void kernel_launch(void* const* d_in, const int* in_sizes, int n_in,
                              void* d_out, int out_size) {
    const float* x   = (const float*)d_in[0];
    const int*   ei  = (const int*)d_in[1];
    const float* W1  = (const float*)d_in[2];
    const float* b1  = (const float*)d_in[3];
    const float* W2  = (const float*)d_in[4];
    const float* b2  = (const float*)d_in[5];
    const float* W3  = (const float*)d_in[6];
    const float* b3  = (const float*)d_in[7];
    const float* Wc1 = (const float*)d_in[8];
    const float* bc1 = (const float*)d_in[9];
    const float* Wc2 = (const float*)d_in[10];
    const float* bc2 = (const float*)d_in[11];
    float* out = (float*)d_out;

    int n = in_sizes[0] / 64;
    int e = in_sizes[1] / 2;
    const int* src = ei;
    const int* dst = ei + e;
    int nb = (n + SCAN_CHUNK - 1) / SCAN_CHUNK;

    __nv_bfloat16* A;  cudaGetSymbolAddress((void**)&A, g_hA);
    __nv_bfloat16* B;  cudaGetSymbolAddress((void**)&B, g_hB);
    int*   edeg;   cudaGetSymbolAddress((void**)&edeg, g_edeg);
    float* pooled; cudaGetSymbolAddress((void**)&pooled, g_pooled);

    const int AGG3_SMEM = (128 * 136 + 128 * 72) * 2;  // 53248 bytes

    // host-side resources, created once on the (uncaptured) correctness call
    static cudaStream_t side = nullptr;
    static cudaEvent_t evA = nullptr, evC = nullptr;
    if (side == nullptr) {
        cudaStreamCreateWithFlags(&side, cudaStreamNonBlocking);
        cudaEventCreateWithFlags(&evA, cudaEventDisableTiming);
        cudaEventCreateWithFlags(&evC, cudaEventDisableTiming);
        cudaFuncSetAttribute(agg_gemm3_kernel,
                             cudaFuncAttributeMaxDynamicSharedMemorySize, AGG3_SMEM);
    }

    // graph prep (default stream)
    cudaMemsetAsync(edeg, 0, (size_t)n * sizeof(int), 0);
    cudaMemsetAsync(pooled, 0, 64 * sizeof(float), 0);
    degree_kernel<<<1024, 256>>>(dst, e);
    scanA_kernel<<<nb, 256>>>(n);                 // deg sums + dis

    // fork: cvt (needs only dis) overlaps scanC + fill on the side stream
    cudaEventRecord(evA, 0);
    cudaStreamWaitEvent(side, evA, 0);
    cvt_kernel<<<1024, 256, 0, side>>>(x, A, n * 8);   // x -> dis-prescaled bf16 (T0)
    cudaEventRecord(evC, side);

    scanC_kernel<<<nb, 256>>>(nb, n);             // offsets
    fill_kernel<<<1024, 256>>>(src, dst, e);      // CSR (in-place cursors)
    cudaStreamWaitEvent(0, evC, 0);               // join before layer 1

    int gg = (n + 127) / 128;
    int ga2 = (n + 15) / 16;  // 2 nodes/warp, 8 warps/block
    // layer 1 FUSED: agg(T0) + gemm1(relu(a@W1+b1)*dis) -> T1 (prescaled)
    agg_gemm1_kernel<<<gg, 512>>>(A, W1, b1, B, n);
    // layer 2 gemm: M2 = T1@W2 (messages, already dis-scaled)
    gemm_tc_kernel<128, 128, false, false><<<gg, 256>>>(B, W2, nullptr, A, n);
    // FUSED agg2 + gemm3: M3 = (relu(dd*sum M2 + b2)*dd) @ W3
    agg_gemm3_kernel<<<gg, 512, AGG3_SMEM>>>(A, W3, b2, B, n);
    // layer 3 agg + mean pool
    agg_pool_kernel<<<ga2, 256>>>(B, b3, n);

    cls_kernel<<<1, 64>>>(Wc1, bc1, Wc2, bc2, out, 1.0f / (float)n);
}